// round 1
// baseline (speedup 1.0000x reference)
#include <cuda_runtime.h>

#define BSZ 4
#define SEQ 2048
#define HID 768
#define AH  384
#define NH  6
#define HD  64
#define KW  9
#define MROWS (BSZ*SEQ)   // 8192

// ---------------- scratch (no allocs allowed) ----------------
__device__ float g_q  [MROWS*AH];
__device__ float g_k  [MROWS*AH];
__device__ float g_v  [MROWS*AH];
__device__ float g_co [MROWS*AH];
__device__ float g_kc [MROWS*AH];
__device__ float g_dwo[MROWS*HID];

// ---------------- generic GEMM: C[M,N] = A[M,768] * W[N,768]^T + bias ----------------
// BM=128, BN=64, BK=16, 256 threads, 8x4 per-thread tile.
__global__ __launch_bounds__(256) void gemm_bias_kernel(
    const float* __restrict__ A, const float* __restrict__ W,
    const float* __restrict__ bias, float* __restrict__ C, int N)
{
    __shared__ float As[16][128];
    __shared__ float Bs[16][64];
    const int tid = threadIdx.x;
    const int tx = tid & 15;      // 16 col-groups
    const int ty = tid >> 4;      // 16 row-groups
    const int m0 = blockIdx.y * 128;
    const int n0 = blockIdx.x * 64;

    float acc[8][4];
#pragma unroll
    for (int i = 0; i < 8; i++)
#pragma unroll
        for (int j = 0; j < 4; j++) acc[i][j] = 0.f;

    for (int k0 = 0; k0 < HID; k0 += 16) {
#pragma unroll
        for (int i = 0; i < 2; i++) {
            int e  = tid + i * 256;          // float4 index into 128x16 tile
            int m  = e >> 2;
            int k4 = (e & 3) << 2;
            float4 va = *(const float4*)(A + (size_t)(m0 + m) * HID + k0 + k4);
            As[k4 + 0][m] = va.x; As[k4 + 1][m] = va.y;
            As[k4 + 2][m] = va.z; As[k4 + 3][m] = va.w;
        }
        {
            int n  = tid >> 2;
            int k4 = (tid & 3) << 2;
            float4 vb = *(const float4*)(W + (size_t)(n0 + n) * HID + k0 + k4);
            Bs[k4 + 0][n] = vb.x; Bs[k4 + 1][n] = vb.y;
            Bs[k4 + 2][n] = vb.z; Bs[k4 + 3][n] = vb.w;
        }
        __syncthreads();
#pragma unroll
        for (int kk = 0; kk < 16; kk++) {
            float4 a0 = *(const float4*)&As[kk][ty * 8];
            float4 a1 = *(const float4*)&As[kk][ty * 8 + 4];
            float4 b0 = *(const float4*)&Bs[kk][tx * 4];
            float a[8] = {a0.x, a0.y, a0.z, a0.w, a1.x, a1.y, a1.z, a1.w};
            float b[4] = {b0.x, b0.y, b0.z, b0.w};
#pragma unroll
            for (int i = 0; i < 8; i++)
#pragma unroll
                for (int j = 0; j < 4; j++)
                    acc[i][j] = fmaf(a[i], b[j], acc[i][j]);
        }
        __syncthreads();
    }

    float4 b4 = *(const float4*)(bias + n0 + tx * 4);
    float bb[4] = {b4.x, b4.y, b4.z, b4.w};
#pragma unroll
    for (int i = 0; i < 8; i++) {
        float4 r;
        r.x = acc[i][0] + bb[0]; r.y = acc[i][1] + bb[1];
        r.z = acc[i][2] + bb[2]; r.w = acc[i][3] + bb[3];
        *(float4*)(C + (size_t)(m0 + ty * 8 + i) * N + n0 + tx * 4) = r;
    }
}

// ---------------- depthwise conv along seq (same padding, K=9) ----------------
__global__ __launch_bounds__(256) void dwconv_kernel(const float* __restrict__ x,
                                                     const float* __restrict__ dw)
{
    int idx = blockIdx.x * 256 + threadIdx.x;     // over MROWS*HID
    int c = idx % HID;
    int r = idx / HID;
    int s = r % SEQ;
    int b = r / SEQ;
    float acc = 0.f;
#pragma unroll
    for (int kk = 0; kk < KW; kk++) {
        int s2 = s + kk - KW / 2;
        if (s2 >= 0 && s2 < SEQ)
            acc = fmaf(x[(size_t)(b * SEQ + s2) * HID + c], dw[c * KW + kk], acc);
    }
    g_dwo[idx] = acc;
}

// ---------------- fused dynamic-span conv: ckl logits -> softmax(9) -> windowed mix ----------------
// one block per (b,s) row; writes out[b,s,384:768]
__global__ __launch_bounds__(384) void convmix_kernel(
    const float* __restrict__ Wck, const float* __restrict__ bck,
    float* __restrict__ out)
{
    __shared__ float ca[AH];
    __shared__ float pr[NH * KW];
    const int r = blockIdx.x;
    const int t = threadIdx.x;

    ca[t] = g_kc[(size_t)r * AH + t] * g_q[(size_t)r * AH + t];
    __syncthreads();

    if (t < NH * KW) {
        const float* w = Wck + t * AH;
        float acc = bck[t];
#pragma unroll 4
        for (int c = 0; c < AH; c++) acc = fmaf(w[c], ca[c], acc);
        pr[t] = acc;
    }
    __syncthreads();

    if (t < NH) {
        float m = -1e30f;
#pragma unroll
        for (int kk = 0; kk < KW; kk++) m = fmaxf(m, pr[t * KW + kk]);
        float e[KW];
        float s = 0.f;
#pragma unroll
        for (int kk = 0; kk < KW; kk++) { e[kk] = __expf(pr[t * KW + kk] - m); s += e[kk]; }
        float inv = 1.f / s;
#pragma unroll
        for (int kk = 0; kk < KW; kk++) pr[t * KW + kk] = e[kk] * inv;
    }
    __syncthreads();

    const int s_ = r % SEQ;
    const int b  = r / SEQ;
    const int h  = t / HD;
    float acc = 0.f;
#pragma unroll
    for (int kk = 0; kk < KW; kk++) {
        int s2 = s_ + kk - KW / 2;
        if (s2 >= 0 && s2 < SEQ)
            acc = fmaf(g_co[(size_t)(b * SEQ + s2) * AH + t], pr[h * KW + kk], acc);
    }
    out[(size_t)r * (2 * AH) + AH + t] = acc;
}

// ---------------- flash-style attention, fp32, 64x64 tiles ----------------
// grid (SEQ/64, BSZ*NH), 256 threads; writes out[b,s,0:384]
// Qs/KPs stored d-major with a 4-column rotation so LDS.128 reads are conflict-free;
// P tile aliases the K buffer (exactly 48KB static smem).
__global__ __launch_bounds__(256) void attn_kernel(float* __restrict__ out)
{
    __shared__ float Qs [64 * 64];   // [d][col=(q + (d&60))&63]
    __shared__ float KPs[64 * 64];   // K: [d][col=(k + (d&60))&63]; then P: [q][k]
    __shared__ float Vs [64 * 64];   // [k][d]
    const int tid = threadIdx.x;
    const int tx = tid & 15;
    const int ty = tid >> 4;
    const int q0 = blockIdx.x * 64;
    const int b  = blockIdx.y / NH;
    const int h  = blockIdx.y % NH;
    const size_t base = (size_t)b * SEQ * AH + h * HD;

    // Q tile (transposed + rotated)
#pragma unroll
    for (int i = 0; i < 4; i++) {
        int e   = tid + i * 256;
        int row = e >> 4;
        int d4  = (e & 15) << 2;
        float4 va = *(const float4*)(g_q + base + (size_t)(q0 + row) * AH + d4);
        int col = (row + d4) & 63;
        Qs[(d4 + 0) * 64 + col] = va.x; Qs[(d4 + 1) * 64 + col] = va.y;
        Qs[(d4 + 2) * 64 + col] = va.z; Qs[(d4 + 3) * 64 + col] = va.w;
    }

    float m_i[4], l_i[4], o[4][4];
#pragma unroll
    for (int i = 0; i < 4; i++) {
        m_i[i] = -1e30f; l_i[i] = 0.f;
#pragma unroll
        for (int j = 0; j < 4; j++) o[i][j] = 0.f;
    }

    for (int kt = 0; kt < SEQ / 64; kt++) {
        __syncthreads();   // prior-iter P/V reads complete before overwrite
#pragma unroll
        for (int i = 0; i < 4; i++) {
            int e   = tid + i * 256;
            int row = e >> 4;
            int d4  = (e & 15) << 2;
            size_t g = base + (size_t)(kt * 64 + row) * AH + d4;
            float4 vk = *(const float4*)(g_k + g);
            int col = (row + d4) & 63;
            KPs[(d4 + 0) * 64 + col] = vk.x; KPs[(d4 + 1) * 64 + col] = vk.y;
            KPs[(d4 + 2) * 64 + col] = vk.z; KPs[(d4 + 3) * 64 + col] = vk.w;
            *(float4*)&Vs[row * 64 + d4] = *(const float4*)(g_v + g);
        }
        __syncthreads();

        // S = Q K^T  (each thread: q rows ty*4.., k cols tx*4..)
        float sc[4][4];
#pragma unroll
        for (int i = 0; i < 4; i++)
#pragma unroll
            for (int j = 0; j < 4; j++) sc[i][j] = 0.f;

        for (int d = 0; d < 64; d++) {
            int shift = d & 60;
            float4 a4 = *(const float4*)&Qs [d * 64 + ((ty * 4 + shift) & 63)];
            float4 b4 = *(const float4*)&KPs[d * 64 + ((tx * 4 + shift) & 63)];
            float a[4]  = {a4.x, a4.y, a4.z, a4.w};
            float bb[4] = {b4.x, b4.y, b4.z, b4.w};
#pragma unroll
            for (int i = 0; i < 4; i++)
#pragma unroll
                for (int j = 0; j < 4; j++)
                    sc[i][j] = fmaf(a[i], bb[j], sc[i][j]);
        }
        __syncthreads();   // done reading KPs as K

        // online softmax update + stage P into KPs
#pragma unroll
        for (int i = 0; i < 4; i++) {
            float mx = fmaxf(fmaxf(sc[i][0], sc[i][1]), fmaxf(sc[i][2], sc[i][3]));
#pragma unroll
            for (int off = 8; off > 0; off >>= 1)
                mx = fmaxf(mx, __shfl_xor_sync(0xffffffffu, mx, off));
            float mnew  = fmaxf(m_i[i], mx * 0.125f);
            float alpha = __expf(m_i[i] - mnew);
            float rs = 0.f;
#pragma unroll
            for (int j = 0; j < 4; j++) {
                sc[i][j] = __expf(sc[i][j] * 0.125f - mnew);
                rs += sc[i][j];
            }
#pragma unroll
            for (int off = 8; off > 0; off >>= 1)
                rs += __shfl_xor_sync(0xffffffffu, rs, off);
            l_i[i] = l_i[i] * alpha + rs;
            m_i[i] = mnew;
#pragma unroll
            for (int j = 0; j < 4; j++) o[i][j] *= alpha;
#pragma unroll
            for (int j = 0; j < 4; j++)
                KPs[(ty * 4 + i) * 64 + tx * 4 + j] = sc[i][j];
        }
        __syncthreads();

        // O += P V  (each thread: q rows ty*4.., d cols tx*4..)
        for (int kr = 0; kr < 64; kr++) {
            float4 v4 = *(const float4*)&Vs[kr * 64 + tx * 4];
            float a0 = KPs[(ty * 4 + 0) * 64 + kr];
            float a1 = KPs[(ty * 4 + 1) * 64 + kr];
            float a2 = KPs[(ty * 4 + 2) * 64 + kr];
            float a3 = KPs[(ty * 4 + 3) * 64 + kr];
            o[0][0] = fmaf(a0, v4.x, o[0][0]); o[0][1] = fmaf(a0, v4.y, o[0][1]);
            o[0][2] = fmaf(a0, v4.z, o[0][2]); o[0][3] = fmaf(a0, v4.w, o[0][3]);
            o[1][0] = fmaf(a1, v4.x, o[1][0]); o[1][1] = fmaf(a1, v4.y, o[1][1]);
            o[1][2] = fmaf(a1, v4.z, o[1][2]); o[1][3] = fmaf(a1, v4.w, o[1][3]);
            o[2][0] = fmaf(a2, v4.x, o[2][0]); o[2][1] = fmaf(a2, v4.y, o[2][1]);
            o[2][2] = fmaf(a2, v4.z, o[2][2]); o[2][3] = fmaf(a2, v4.w, o[2][3]);
            o[3][0] = fmaf(a3, v4.x, o[3][0]); o[3][1] = fmaf(a3, v4.y, o[3][1]);
            o[3][2] = fmaf(a3, v4.z, o[3][2]); o[3][3] = fmaf(a3, v4.w, o[3][3]);
        }
    }

#pragma unroll
    for (int i = 0; i < 4; i++) {
        float inv = 1.f / l_i[i];
        float4 r;
        r.x = o[i][0] * inv; r.y = o[i][1] * inv;
        r.z = o[i][2] * inv; r.w = o[i][3] * inv;
        *(float4*)(out + (size_t)(b * SEQ + q0 + ty * 4 + i) * (2 * AH) + h * HD + tx * 4) = r;
    }
}

// ---------------- launch ----------------
extern "C" void kernel_launch(void* const* d_in, const int* in_sizes, int n_in,
                              void* d_out, int out_size)
{
    (void)in_sizes; (void)n_in; (void)out_size;
    const float* x   = (const float*)d_in[0];
    const float* Wq  = (const float*)d_in[1];
    const float* bq  = (const float*)d_in[2];
    const float* Wk  = (const float*)d_in[3];
    const float* bk  = (const float*)d_in[4];
    const float* Wv  = (const float*)d_in[5];
    const float* bv  = (const float*)d_in[6];
    const float* dw  = (const float*)d_in[7];
    const float* pw  = (const float*)d_in[8];
    const float* cb  = (const float*)d_in[9];
    const float* Wck = (const float*)d_in[10];
    const float* bck = (const float*)d_in[11];
    const float* Wco = (const float*)d_in[12];
    const float* bco = (const float*)d_in[13];
    float* out = (float*)d_out;

    float *qp, *kp, *vp, *cop, *kcp, *dwop;
    cudaGetSymbolAddress((void**)&qp,   g_q);
    cudaGetSymbolAddress((void**)&kp,   g_k);
    cudaGetSymbolAddress((void**)&vp,   g_v);
    cudaGetSymbolAddress((void**)&cop,  g_co);
    cudaGetSymbolAddress((void**)&kcp,  g_kc);
    cudaGetSymbolAddress((void**)&dwop, g_dwo);

    dim3 gg(AH / 64, MROWS / 128);
    gemm_bias_kernel<<<gg, 256>>>(x, Wq,  bq,  qp,  AH);
    gemm_bias_kernel<<<gg, 256>>>(x, Wk,  bk,  kp,  AH);
    gemm_bias_kernel<<<gg, 256>>>(x, Wv,  bv,  vp,  AH);
    gemm_bias_kernel<<<gg, 256>>>(x, Wco, bco, cop, AH);
    dwconv_kernel<<<(MROWS * HID) / 256, 256>>>(x, dw);
    gemm_bias_kernel<<<gg, 256>>>(dwop, pw, cb, kcp, AH);
    convmix_kernel<<<MROWS, 384>>>(Wck, bck, out);
    attn_kernel<<<dim3(SEQ / 64, BSZ * NH), 256>>>(out);
}

// round 5
// speedup vs baseline: 1.7228x; 1.7228x over previous
#include <cuda_runtime.h>
#include <cstdint>

#define BSZ 4
#define SEQ 2048
#define HID 768
#define AH  384
#define NH  6
#define HD  64
#define KW  9
#define MROWS (BSZ*SEQ)   // 8192

// ---------------- scratch (no allocs allowed) ----------------
__device__ float g_q  [MROWS*AH];
__device__ float g_k  [MROWS*AH];
__device__ float g_v  [MROWS*AH];
__device__ float g_co [MROWS*AH];
__device__ float g_kc [MROWS*AH];
__device__ float g_dwo[MROWS*HID];
__device__ float g_xr [MROWS*HID];     // x rounded to tf32
__device__ float g_wr [5*AH*HID];      // Wq,Wk,Wv,Wco,pw rounded to tf32

// ================= helpers =================
__device__ __forceinline__ uint32_t smem_u32(const void* p) {
    uint32_t a;
    asm("{ .reg .u64 t; cvta.to.shared.u64 t, %1; cvt.u32.u64 %0, t; }" : "=r"(a) : "l"(p));
    return a;
}
__device__ __forceinline__ uint32_t f2tf(float x) {       // round fp32 -> tf32 bits (RNA)
    uint32_t r;
    asm("cvt.rna.tf32.f32 %0, %1;" : "=r"(r) : "f"(x));
    return r;
}
__device__ __forceinline__ float f2tff(float x) { return __uint_as_float(f2tf(x)); }

// m16n8k8 tf32 mma: D(16x8,f32) += A(16x8,tf32) * B(8x8,tf32 col-major)
__device__ __forceinline__ void mma_tf32(float* c, const uint32_t* a, const uint32_t* b) {
    asm volatile(
        "mma.sync.aligned.m16n8k8.row.col.f32.tf32.tf32.f32 "
        "{%0,%1,%2,%3}, {%4,%5,%6,%7}, {%8,%9}, {%0,%1,%2,%3};"
        : "+f"(c[0]), "+f"(c[1]), "+f"(c[2]), "+f"(c[3])
        : "r"(a[0]), "r"(a[1]), "r"(a[2]), "r"(a[3]), "r"(b[0]), "r"(b[1]));
}

// ---------------- round fp32 -> tf32 (RNA) ----------------
__global__ __launch_bounds__(256) void round_tf32_kernel(const float* __restrict__ in,
                                                         float* __restrict__ out, int n4)
{
    int i = blockIdx.x * 256 + threadIdx.x;
    if (i >= n4) return;
    float4 v = ((const float4*)in)[i];
    float4 r;
    r.x = f2tff(v.x); r.y = f2tff(v.y); r.z = f2tff(v.z); r.w = f2tff(v.w);
    ((float4*)out)[i] = r;
}

// ---------------- tf32 mma GEMM: C[8192,384] = A[8192,768] @ W[384,768]^T + bias ----------
// CTA 128x128, 8 warps (2m x 4n), warp tile 64x32, BK=32, cp.async double buffer.
#define APITCH 36                      // floats; 36%32=4 -> conflict-free frag loads
#define STG_FLTS (2*128*APITCH)        // A + B per stage = 9216 floats

__global__ __launch_bounds__(256) void gemm_mma_kernel(
    const float* __restrict__ A, const float* __restrict__ W,
    const float* __restrict__ bias, float* __restrict__ C)
{
    extern __shared__ float smem[];    // 2 * 9216 floats = 73728 B
    const int tid = threadIdx.x, lane = tid & 31, wid = tid >> 5;
    const int wm = (wid >> 2) * 64;    // warp m offset in tile
    const int wn = (wid & 3) * 32;     // warp n offset in tile
    const int m0 = blockIdx.y * 128, n0 = blockIdx.x * 128;
    const int g4 = lane >> 2, t4 = lane & 3;   // groupID, threadID_in_group

    float c[4][4][4];
#pragma unroll
    for (int mt = 0; mt < 4; mt++)
#pragma unroll
        for (int nt = 0; nt < 4; nt++)
#pragma unroll
            for (int j = 0; j < 4; j++) c[mt][nt][j] = 0.f;

    auto load_stage = [&](int s, int kb) {
        float* sb = smem + s * STG_FLTS;
#pragma unroll
        for (int ci = 0; ci < 4; ci++) {
            int e = tid + ci * 256;          // 1024 chunks of 16B for A
            int row = e >> 3, k4 = (e & 7) << 2;
            uint32_t dst = smem_u32(sb + row * APITCH + k4);
            const float* g = A + (size_t)(m0 + row) * HID + kb + k4;
            asm volatile("cp.async.cg.shared.global [%0], [%1], 16;" :: "r"(dst), "l"(g));
        }
#pragma unroll
        for (int ci = 0; ci < 4; ci++) {
            int e = tid + ci * 256;          // 1024 chunks for B
            int row = e >> 3, k4 = (e & 7) << 2;
            uint32_t dst = smem_u32(sb + 128 * APITCH + row * APITCH + k4);
            const float* g = W + (size_t)(n0 + row) * HID + kb + k4;
            asm volatile("cp.async.cg.shared.global [%0], [%1], 16;" :: "r"(dst), "l"(g));
        }
        asm volatile("cp.async.commit_group;" ::: "memory");
    };

    load_stage(0, 0);
    load_stage(1, 32);

    for (int i = 0; i < 24; i++) {
        const int s = i & 1;
        if (i < 23) asm volatile("cp.async.wait_group 1;" ::: "memory");
        else        asm volatile("cp.async.wait_group 0;" ::: "memory");
        __syncthreads();

        const float* as = smem + s * STG_FLTS;
        const float* bs = as + 128 * APITCH;
#pragma unroll
        for (int ks = 0; ks < 4; ks++) {
            const int col = ks * 8 + t4;
            uint32_t af[4][4], bf[4][2];
#pragma unroll
            for (int mt = 0; mt < 4; mt++) {
                const float* p = as + (wm + mt * 16 + g4) * APITCH;
                af[mt][0] = __float_as_uint(p[col]);
                af[mt][1] = __float_as_uint(p[8 * APITCH + col]);
                af[mt][2] = __float_as_uint(p[col + 4]);
                af[mt][3] = __float_as_uint(p[8 * APITCH + col + 4]);
            }
#pragma unroll
            for (int nt = 0; nt < 4; nt++) {
                const float* p = bs + (wn + nt * 8 + g4) * APITCH;
                bf[nt][0] = __float_as_uint(p[col]);
                bf[nt][1] = __float_as_uint(p[col + 4]);
            }
#pragma unroll
            for (int mt = 0; mt < 4; mt++)
#pragma unroll
                for (int nt = 0; nt < 4; nt++)
                    mma_tf32(c[mt][nt], af[mt], bf[nt]);
        }
        __syncthreads();
        if (i + 2 < 24) load_stage(s, (i + 2) * 32);
    }

    // epilogue: bias + store
#pragma unroll
    for (int mt = 0; mt < 4; mt++) {
        int row = m0 + wm + mt * 16 + g4;
#pragma unroll
        for (int nt = 0; nt < 4; nt++) {
            int col = n0 + wn + nt * 8 + 2 * t4;
            float b0 = __ldg(bias + col), b1 = __ldg(bias + col + 1);
            float2 r0 = make_float2(c[mt][nt][0] + b0, c[mt][nt][1] + b1);
            float2 r1 = make_float2(c[mt][nt][2] + b0, c[mt][nt][3] + b1);
            *(float2*)(C + (size_t)row * AH + col)       = r0;
            *(float2*)(C + (size_t)(row + 8) * AH + col) = r1;
        }
    }
}

// ---------------- depthwise conv along seq (same padding, K=9); output tf32-rounded -------
__global__ __launch_bounds__(256) void dwconv_kernel(const float* __restrict__ x,
                                                     const float* __restrict__ dw)
{
    int idx = blockIdx.x * 256 + threadIdx.x;
    int c = idx % HID;
    int r = idx / HID;
    int s = r % SEQ;
    int b = r / SEQ;
    float acc = 0.f;
#pragma unroll
    for (int kk = 0; kk < KW; kk++) {
        int s2 = s + kk - KW / 2;
        if (s2 >= 0 && s2 < SEQ)
            acc = fmaf(x[(size_t)(b * SEQ + s2) * HID + c], dw[c * KW + kk], acc);
    }
    g_dwo[idx] = f2tff(acc);
}

// ---------------- fused dynamic-span conv ----------------
__global__ __launch_bounds__(384) void convmix_kernel(
    const float* __restrict__ Wck, const float* __restrict__ bck,
    float* __restrict__ out)
{
    __shared__ float ca[AH];
    __shared__ float pr[NH * KW];
    const int r = blockIdx.x;
    const int t = threadIdx.x;

    ca[t] = g_kc[(size_t)r * AH + t] * g_q[(size_t)r * AH + t];
    __syncthreads();

    if (t < NH * KW) {
        const float* w = Wck + t * AH;
        float acc = bck[t];
#pragma unroll 4
        for (int c = 0; c < AH; c++) acc = fmaf(w[c], ca[c], acc);
        pr[t] = acc;
    }
    __syncthreads();

    if (t < NH) {
        float m = -1e30f;
#pragma unroll
        for (int kk = 0; kk < KW; kk++) m = fmaxf(m, pr[t * KW + kk]);
        float e[KW];
        float s = 0.f;
#pragma unroll
        for (int kk = 0; kk < KW; kk++) { e[kk] = __expf(pr[t * KW + kk] - m); s += e[kk]; }
        float inv = 1.f / s;
#pragma unroll
        for (int kk = 0; kk < KW; kk++) pr[t * KW + kk] = e[kk] * inv;
    }
    __syncthreads();

    const int s_ = r % SEQ;
    const int b  = r / SEQ;
    const int h  = t / HD;
    float acc = 0.f;
#pragma unroll
    for (int kk = 0; kk < KW; kk++) {
        int s2 = s_ + kk - KW / 2;
        if (s2 >= 0 && s2 < SEQ)
            acc = fmaf(g_co[(size_t)(b * SEQ + s2) * AH + t], pr[h * KW + kk], acc);
    }
    out[(size_t)r * (2 * AH) + AH + t] = acc;
}

// ---------------- flash attention with tf32 mma.sync ----------------
// CTA: 64 q-rows, 4 warps (16 rows each, full row ownership), 32 KV tiles of 64.
// Ks: [key][d] pitch 68 (bank = 4*g4+t4, conflict-free fragment loads)
// Vt: [d][key] pitch 68 (transposed -> conflict-free B-fragment loads)
// Ps: per-warp P patch, pitch 68
#define KP  68
#define VPT 68
#define PP  68
// smem floats: Ks 64*68 + Vt 64*68 + Ps 4*16*68 = 13056 -> 52224 B
__global__ __launch_bounds__(128) void attn_mma_kernel(float* __restrict__ out)
{
    extern __shared__ float smem[];
    float* Ks = smem;
    float* Vt = Ks + 64 * KP;
    float* Ps = Vt + 64 * VPT;

    const int tid = threadIdx.x, lane = tid & 31, w = tid >> 5;
    const int g4 = lane >> 2, t4 = lane & 3;
    const int q0 = blockIdx.x * 64;
    const int b  = blockIdx.y / NH;
    const int h  = blockIdx.y % NH;
    const size_t base = (size_t)b * SEQ * AH + h * HD;

    // ---- stage Q into Ks, read A-fragments, then Ks is reused for K ----
#pragma unroll
    for (int i = 0; i < 8; i++) {
        int e = tid + i * 128;
        int row = e >> 4, d4 = (e & 15) << 2;
        float4 v = *(const float4*)(g_q + base + (size_t)(q0 + row) * AH + d4);
        float* p = Ks + row * KP + d4;
        p[0] = f2tff(v.x); p[1] = f2tff(v.y); p[2] = f2tff(v.z); p[3] = f2tff(v.w);
    }
    __syncthreads();
    uint32_t qa[8][4];
    {
        const float* p0 = Ks + (w * 16 + g4) * KP;
        const float* p1 = p0 + 8 * KP;
#pragma unroll
        for (int ds = 0; ds < 8; ds++) {
            int col = ds * 8 + t4;
            qa[ds][0] = __float_as_uint(p0[col]);
            qa[ds][1] = __float_as_uint(p1[col]);
            qa[ds][2] = __float_as_uint(p0[col + 4]);
            qa[ds][3] = __float_as_uint(p1[col + 4]);
        }
    }

    float o[8][4];
#pragma unroll
    for (int dt = 0; dt < 8; dt++)
#pragma unroll
        for (int j = 0; j < 4; j++) o[dt][j] = 0.f;
    float m0 = -1e30f, m1 = -1e30f, l0 = 0.f, l1 = 0.f;

    float* pw = Ps + w * 16 * PP;

    for (int kt = 0; kt < 32; kt++) {
        __syncthreads();   // Q frags read / prior-iter Vt reads done
#pragma unroll
        for (int i = 0; i < 8; i++) {
            int e = tid + i * 128;
            int row = e >> 4, d4 = (e & 15) << 2;
            size_t g = base + (size_t)(kt * 64 + row) * AH + d4;
            float4 kv = *(const float4*)(g_k + g);
            float4 vv = *(const float4*)(g_v + g);
            float* pk = Ks + row * KP + d4;
            pk[0] = f2tff(kv.x); pk[1] = f2tff(kv.y); pk[2] = f2tff(kv.z); pk[3] = f2tff(kv.w);
            Vt[(d4 + 0) * VPT + row] = f2tff(vv.x);
            Vt[(d4 + 1) * VPT + row] = f2tff(vv.y);
            Vt[(d4 + 2) * VPT + row] = f2tff(vv.z);
            Vt[(d4 + 3) * VPT + row] = f2tff(vv.w);
        }
        __syncthreads();

        // S = Q K^T
        float s[8][4];
#pragma unroll
        for (int nt = 0; nt < 8; nt++)
#pragma unroll
            for (int j = 0; j < 4; j++) s[nt][j] = 0.f;
#pragma unroll
        for (int ds = 0; ds < 8; ds++) {
            int col = ds * 8 + t4;
#pragma unroll
            for (int nt = 0; nt < 8; nt++) {
                uint32_t bf[2];
                const float* p = Ks + (nt * 8 + g4) * KP;
                bf[0] = __float_as_uint(p[col]);
                bf[1] = __float_as_uint(p[col + 4]);
                mma_tf32(s[nt], qa[ds], bf);
            }
        }

        // online softmax (rows g4 and g4+8)
        float mx0 = -1e30f, mx1 = -1e30f;
#pragma unroll
        for (int nt = 0; nt < 8; nt++) {
            mx0 = fmaxf(mx0, fmaxf(s[nt][0], s[nt][1]));
            mx1 = fmaxf(mx1, fmaxf(s[nt][2], s[nt][3]));
        }
#pragma unroll
        for (int off = 1; off <= 2; off <<= 1) {
            mx0 = fmaxf(mx0, __shfl_xor_sync(0xffffffffu, mx0, off));
            mx1 = fmaxf(mx1, __shfl_xor_sync(0xffffffffu, mx1, off));
        }
        float mn0 = fmaxf(m0, mx0 * 0.125f);
        float mn1 = fmaxf(m1, mx1 * 0.125f);
        float a0 = __expf(m0 - mn0), a1 = __expf(m1 - mn1);
        float rs0 = 0.f, rs1 = 0.f;
#pragma unroll
        for (int nt = 0; nt < 8; nt++) {
            s[nt][0] = __expf(s[nt][0] * 0.125f - mn0);
            s[nt][1] = __expf(s[nt][1] * 0.125f - mn0);
            s[nt][2] = __expf(s[nt][2] * 0.125f - mn1);
            s[nt][3] = __expf(s[nt][3] * 0.125f - mn1);
            rs0 += s[nt][0] + s[nt][1];
            rs1 += s[nt][2] + s[nt][3];
        }
#pragma unroll
        for (int off = 1; off <= 2; off <<= 1) {
            rs0 += __shfl_xor_sync(0xffffffffu, rs0, off);
            rs1 += __shfl_xor_sync(0xffffffffu, rs1, off);
        }
        l0 = l0 * a0 + rs0; l1 = l1 * a1 + rs1;
        m0 = mn0; m1 = mn1;
#pragma unroll
        for (int dt = 0; dt < 8; dt++) {
            o[dt][0] *= a0; o[dt][1] *= a0;
            o[dt][2] *= a1; o[dt][3] *= a1;
        }

        // P -> per-warp smem patch (tf32-rounded)
#pragma unroll
        for (int nt = 0; nt < 8; nt++) {
            int col = nt * 8 + 2 * t4;
            *(float2*)(pw + g4 * PP + col) =
                make_float2(__uint_as_float(f2tf(s[nt][0])), __uint_as_float(f2tf(s[nt][1])));
            *(float2*)(pw + (g4 + 8) * PP + col) =
                make_float2(__uint_as_float(f2tf(s[nt][2])), __uint_as_float(f2tf(s[nt][3])));
        }
        __syncwarp();

        // O += P V   (B-fragments from transposed Vt, conflict-free)
#pragma unroll
        for (int ks = 0; ks < 8; ks++) {
            int col = ks * 8 + t4;
            uint32_t pa[4];
            pa[0] = __float_as_uint(pw[g4 * PP + col]);
            pa[1] = __float_as_uint(pw[(g4 + 8) * PP + col]);
            pa[2] = __float_as_uint(pw[g4 * PP + col + 4]);
            pa[3] = __float_as_uint(pw[(g4 + 8) * PP + col + 4]);
#pragma unroll
            for (int dt = 0; dt < 8; dt++) {
                uint32_t bf[2];
                const float* vp = Vt + (dt * 8 + g4) * VPT + ks * 8;
                bf[0] = __float_as_uint(vp[t4]);
                bf[1] = __float_as_uint(vp[t4 + 4]);
                mma_tf32(o[dt], pa, bf);
            }
        }
    }

    // final: normalize + store
    float inv0 = 1.f / l0, inv1 = 1.f / l1;
    const int row = b * SEQ + q0 + w * 16 + g4;
#pragma unroll
    for (int dt = 0; dt < 8; dt++) {
        int col = h * HD + dt * 8 + 2 * t4;
        *(float2*)(out + (size_t)row * (2 * AH) + col) =
            make_float2(o[dt][0] * inv0, o[dt][1] * inv0);
        *(float2*)(out + (size_t)(row + 8) * (2 * AH) + col) =
            make_float2(o[dt][2] * inv1, o[dt][3] * inv1);
    }
}

// ---------------- launch ----------------
extern "C" void kernel_launch(void* const* d_in, const int* in_sizes, int n_in,
                              void* d_out, int out_size)
{
    (void)in_sizes; (void)n_in; (void)out_size;
    const float* x   = (const float*)d_in[0];
    const float* Wq  = (const float*)d_in[1];
    const float* bq  = (const float*)d_in[2];
    const float* Wk  = (const float*)d_in[3];
    const float* bk  = (const float*)d_in[4];
    const float* Wv  = (const float*)d_in[5];
    const float* bv  = (const float*)d_in[6];
    const float* dw  = (const float*)d_in[7];
    const float* pw  = (const float*)d_in[8];
    const float* cb  = (const float*)d_in[9];
    const float* Wck = (const float*)d_in[10];
    const float* bck = (const float*)d_in[11];
    const float* Wco = (const float*)d_in[12];
    const float* bco = (const float*)d_in[13];
    float* out = (float*)d_out;

    float *qp, *kp, *vp, *cop, *kcp, *dwop, *xrp, *wrp;
    cudaGetSymbolAddress((void**)&qp,   g_q);
    cudaGetSymbolAddress((void**)&kp,   g_k);
    cudaGetSymbolAddress((void**)&vp,   g_v);
    cudaGetSymbolAddress((void**)&cop,  g_co);
    cudaGetSymbolAddress((void**)&kcp,  g_kc);
    cudaGetSymbolAddress((void**)&dwop, g_dwo);
    cudaGetSymbolAddress((void**)&xrp,  g_xr);
    cudaGetSymbolAddress((void**)&wrp,  g_wr);

    cudaFuncSetAttribute(gemm_mma_kernel, cudaFuncAttributeMaxDynamicSharedMemorySize,
                         2 * STG_FLTS * 4);
    cudaFuncSetAttribute(attn_mma_kernel, cudaFuncAttributeMaxDynamicSharedMemorySize, 52224);

    const int WN4 = (AH * HID) / 4;
    round_tf32_kernel<<<(MROWS * HID / 4 + 255) / 256, 256>>>(x,   xrp, MROWS * HID / 4);
    round_tf32_kernel<<<(WN4 + 255) / 256, 256>>>(Wq,  wrp + 0 * AH * HID, WN4);
    round_tf32_kernel<<<(WN4 + 255) / 256, 256>>>(Wk,  wrp + 1 * AH * HID, WN4);
    round_tf32_kernel<<<(WN4 + 255) / 256, 256>>>(Wv,  wrp + 2 * AH * HID, WN4);
    round_tf32_kernel<<<(WN4 + 255) / 256, 256>>>(Wco, wrp + 3 * AH * HID, WN4);
    round_tf32_kernel<<<(WN4 + 255) / 256, 256>>>(pw,  wrp + 4 * AH * HID, WN4);
    dwconv_kernel<<<(MROWS * HID) / 256, 256>>>(x, dw);

    dim3 gg(AH / 128, MROWS / 128);   // (3, 64)
    gemm_mma_kernel<<<gg, 256, 2 * STG_FLTS * 4>>>(xrp,  wrp + 0 * AH * HID, bq,  qp);
    gemm_mma_kernel<<<gg, 256, 2 * STG_FLTS * 4>>>(xrp,  wrp + 1 * AH * HID, bk,  kp);
    gemm_mma_kernel<<<gg, 256, 2 * STG_FLTS * 4>>>(xrp,  wrp + 2 * AH * HID, bv,  vp);
    gemm_mma_kernel<<<gg, 256, 2 * STG_FLTS * 4>>>(xrp,  wrp + 3 * AH * HID, bco, cop);
    gemm_mma_kernel<<<gg, 256, 2 * STG_FLTS * 4>>>(dwop, wrp + 4 * AH * HID, cb,  kcp);

    convmix_kernel<<<MROWS, 384>>>(Wck, bck, out);
    attn_mma_kernel<<<dim3(SEQ / 64, BSZ * NH), 128, 52224>>>(out);
}

// round 7
// speedup vs baseline: 1.7389x; 1.0093x over previous
#include <cuda_runtime.h>
#include <cstdint>

#define BSZ 4
#define SEQ 2048
#define HID 768
#define AH  384
#define NH  6
#define HD  64
#define KW  9
#define MROWS (BSZ*SEQ)   // 8192

// ---------------- scratch (no allocs allowed) ----------------
__device__ float g_q  [MROWS*AH];
__device__ float g_k  [MROWS*AH];
__device__ float g_v  [MROWS*AH];
__device__ float g_co [MROWS*AH];
__device__ float g_kc [MROWS*AH];
__device__ float g_dwo[MROWS*HID];
__device__ float g_xr [MROWS*HID];     // x rounded to tf32
__device__ float g_wr [5*AH*HID];      // Wq,Wk,Wv,Wco,pw rounded to tf32

// ================= helpers =================
__device__ __forceinline__ uint32_t smem_u32(const void* p) {
    uint32_t a;
    asm("{ .reg .u64 t; cvta.to.shared.u64 t, %1; cvt.u32.u64 %0, t; }" : "=r"(a) : "l"(p));
    return a;
}
__device__ __forceinline__ uint32_t f2tf(float x) {       // round fp32 -> tf32 bits (RNA)
    uint32_t r;
    asm("cvt.rna.tf32.f32 %0, %1;" : "=r"(r) : "f"(x));
    return r;
}
__device__ __forceinline__ float f2tff(float x) { return __uint_as_float(f2tf(x)); }

// m16n8k8 tf32 mma: D(16x8,f32) += A(16x8,tf32) * B(8x8,tf32 col-major)
__device__ __forceinline__ void mma_tf32(float* c, const uint32_t* a, const uint32_t* b) {
    asm volatile(
        "mma.sync.aligned.m16n8k8.row.col.f32.tf32.tf32.f32 "
        "{%0,%1,%2,%3}, {%4,%5,%6,%7}, {%8,%9}, {%0,%1,%2,%3};"
        : "+f"(c[0]), "+f"(c[1]), "+f"(c[2]), "+f"(c[3])
        : "r"(a[0]), "r"(a[1]), "r"(a[2]), "r"(a[3]), "r"(b[0]), "r"(b[1]));
}

// ---------------- fused rounding of x + all 5 weights (one launch) ----------------
#define XN4 (MROWS*HID/4)       // 1572864 float4
#define WN4 (AH*HID/4)          // 73728 float4 per weight
__global__ __launch_bounds__(256) void round_all_kernel(
    const float* __restrict__ x,
    const float* __restrict__ Wq, const float* __restrict__ Wk,
    const float* __restrict__ Wv, const float* __restrict__ Wco,
    const float* __restrict__ pw,
    float* __restrict__ xr, float* __restrict__ wr)
{
    int i = blockIdx.x * 256 + threadIdx.x;
    const float4* src;
    float4* dst;
    int off;
    if (i < XN4) { src = (const float4*)x; dst = (float4*)xr; off = i; }
    else {
        int j = i - XN4;
        int sel = j / WN4;
        off = j - sel * WN4;
        const float* ws[5] = {Wq, Wk, Wv, Wco, pw};
        if (sel >= 5) return;
        src = (const float4*)ws[sel];
        dst = (float4*)(wr + sel * (AH * HID));
    }
    float4 v = src[off];
    float4 r;
    r.x = f2tff(v.x); r.y = f2tff(v.y); r.z = f2tff(v.z); r.w = f2tff(v.w);
    dst[off] = r;
}

// ---------------- tf32 mma GEMM: C[8192,384] = A[8192,768] @ W[384,768]^T + bias ----------
#define APITCH 36
#define STG_FLTS (2*128*APITCH)

__global__ __launch_bounds__(256) void gemm_mma_kernel(
    const float* __restrict__ A, const float* __restrict__ W,
    const float* __restrict__ bias, float* __restrict__ C)
{
    extern __shared__ float smem[];
    const int tid = threadIdx.x, lane = tid & 31, wid = tid >> 5;
    const int wm = (wid >> 2) * 64;
    const int wn = (wid & 3) * 32;
    const int m0 = blockIdx.y * 128, n0 = blockIdx.x * 128;
    const int g4 = lane >> 2, t4 = lane & 3;

    float c[4][4][4];
#pragma unroll
    for (int mt = 0; mt < 4; mt++)
#pragma unroll
        for (int nt = 0; nt < 4; nt++)
#pragma unroll
            for (int j = 0; j < 4; j++) c[mt][nt][j] = 0.f;

    auto load_stage = [&](int s, int kb) {
        float* sb = smem + s * STG_FLTS;
#pragma unroll
        for (int ci = 0; ci < 4; ci++) {
            int e = tid + ci * 256;
            int row = e >> 3, k4 = (e & 7) << 2;
            uint32_t dst = smem_u32(sb + row * APITCH + k4);
            const float* g = A + (size_t)(m0 + row) * HID + kb + k4;
            asm volatile("cp.async.cg.shared.global [%0], [%1], 16;" :: "r"(dst), "l"(g));
        }
#pragma unroll
        for (int ci = 0; ci < 4; ci++) {
            int e = tid + ci * 256;
            int row = e >> 3, k4 = (e & 7) << 2;
            uint32_t dst = smem_u32(sb + 128 * APITCH + row * APITCH + k4);
            const float* g = W + (size_t)(n0 + row) * HID + kb + k4;
            asm volatile("cp.async.cg.shared.global [%0], [%1], 16;" :: "r"(dst), "l"(g));
        }
        asm volatile("cp.async.commit_group;" ::: "memory");
    };

    load_stage(0, 0);
    load_stage(1, 32);

    for (int i = 0; i < 24; i++) {
        const int s = i & 1;
        if (i < 23) asm volatile("cp.async.wait_group 1;" ::: "memory");
        else        asm volatile("cp.async.wait_group 0;" ::: "memory");
        __syncthreads();

        const float* as = smem + s * STG_FLTS;
        const float* bs = as + 128 * APITCH;
#pragma unroll
        for (int ks = 0; ks < 4; ks++) {
            const int col = ks * 8 + t4;
            uint32_t af[4][4], bf[4][2];
#pragma unroll
            for (int mt = 0; mt < 4; mt++) {
                const float* p = as + (wm + mt * 16 + g4) * APITCH;
                af[mt][0] = __float_as_uint(p[col]);
                af[mt][1] = __float_as_uint(p[8 * APITCH + col]);
                af[mt][2] = __float_as_uint(p[col + 4]);
                af[mt][3] = __float_as_uint(p[8 * APITCH + col + 4]);
            }
#pragma unroll
            for (int nt = 0; nt < 4; nt++) {
                const float* p = bs + (wn + nt * 8 + g4) * APITCH;
                bf[nt][0] = __float_as_uint(p[col]);
                bf[nt][1] = __float_as_uint(p[col + 4]);
            }
#pragma unroll
            for (int mt = 0; mt < 4; mt++)
#pragma unroll
                for (int nt = 0; nt < 4; nt++)
                    mma_tf32(c[mt][nt], af[mt], bf[nt]);
        }
        __syncthreads();
        if (i + 2 < 24) load_stage(s, (i + 2) * 32);
    }

#pragma unroll
    for (int mt = 0; mt < 4; mt++) {
        int row = m0 + wm + mt * 16 + g4;
#pragma unroll
        for (int nt = 0; nt < 4; nt++) {
            int col = n0 + wn + nt * 8 + 2 * t4;
            float b0 = __ldg(bias + col), b1 = __ldg(bias + col + 1);
            float2 r0 = make_float2(c[mt][nt][0] + b0, c[mt][nt][1] + b1);
            float2 r1 = make_float2(c[mt][nt][2] + b0, c[mt][nt][3] + b1);
            *(float2*)(C + (size_t)row * AH + col)       = r0;
            *(float2*)(C + (size_t)(row + 8) * AH + col) = r1;
        }
    }
}

// ---------------- depthwise conv along seq (same padding, K=9); output tf32-rounded -------
__global__ __launch_bounds__(256) void dwconv_kernel(const float* __restrict__ x,
                                                     const float* __restrict__ dw)
{
    int idx = blockIdx.x * 256 + threadIdx.x;
    int c = idx % HID;
    int r = idx / HID;
    int s = r % SEQ;
    int b = r / SEQ;
    float acc = 0.f;
#pragma unroll
    for (int kk = 0; kk < KW; kk++) {
        int s2 = s + kk - KW / 2;
        if (s2 >= 0 && s2 < SEQ)
            acc = fmaf(x[(size_t)(b * SEQ + s2) * HID + c], dw[c * KW + kk], acc);
    }
    g_dwo[idx] = f2tff(acc);
}

// ---------------- fused dynamic-span conv ----------------
__global__ __launch_bounds__(384) void convmix_kernel(
    const float* __restrict__ Wck, const float* __restrict__ bck,
    float* __restrict__ out)
{
    __shared__ float ca[AH];
    __shared__ float pr[NH * KW];
    const int r = blockIdx.x;
    const int t = threadIdx.x;

    ca[t] = g_kc[(size_t)r * AH + t] * g_q[(size_t)r * AH + t];
    __syncthreads();

    if (t < NH * KW) {
        const float* w = Wck + t * AH;
        float acc = bck[t];
#pragma unroll 4
        for (int c = 0; c < AH; c++) acc = fmaf(w[c], ca[c], acc);
        pr[t] = acc;
    }
    __syncthreads();

    if (t < NH) {
        float m = -1e30f;
#pragma unroll
        for (int kk = 0; kk < KW; kk++) m = fmaxf(m, pr[t * KW + kk]);
        float e[KW];
        float s = 0.f;
#pragma unroll
        for (int kk = 0; kk < KW; kk++) { e[kk] = __expf(pr[t * KW + kk] - m); s += e[kk]; }
        float inv = 1.f / s;
#pragma unroll
        for (int kk = 0; kk < KW; kk++) pr[t * KW + kk] = e[kk] * inv;
    }
    __syncthreads();

    const int s_ = r % SEQ;
    const int b  = r / SEQ;
    const int h  = t / HD;
    float acc = 0.f;
#pragma unroll
    for (int kk = 0; kk < KW; kk++) {
        int s2 = s_ + kk - KW / 2;
        if (s2 >= 0 && s2 < SEQ)
            acc = fmaf(g_co[(size_t)(b * SEQ + s2) * AH + t], pr[h * KW + kk], acc);
    }
    out[(size_t)r * (2 * AH) + AH + t] = acc;
}

// ---------------- flash attention with tf32 mma.sync ----------------
// CTA: 128 q-rows, 8 warps (16 rows each), 32 KV tiles of 64 keys.
// Ks: [key][d] pitch 68; Vt: [d][key] pitch 68; Ps: per-warp P patch (also Q staging)
#define KP  68
#define VPT 68
#define PP  68
// smem floats: Ks 64*68 + Vt 64*68 + Ps 128*68 = 17408 -> 69632 B
__global__ __launch_bounds__(256) void attn_mma_kernel(float* __restrict__ out)
{
    extern __shared__ float smem[];
    float* Ks = smem;
    float* Vt = Ks + 64 * KP;
    float* Ps = Vt + 64 * VPT;

    const int tid = threadIdx.x, lane = tid & 31, w = tid >> 5;
    const int g4 = lane >> 2, t4 = lane & 3;
    const int q0 = blockIdx.x * 128;
    const int b  = blockIdx.y / NH;
    const int h  = blockIdx.y % NH;
    const size_t base = (size_t)b * SEQ * AH + h * HD;

    // ---- stage Q (128 rows) into Ps, read per-warp A-fragments ----
#pragma unroll
    for (int i = 0; i < 8; i++) {
        int e = tid + i * 256;               // 2048 float4 chunks
        int row = e >> 4, d4 = (e & 15) << 2;
        float4 v = *(const float4*)(g_q + base + (size_t)(q0 + row) * AH + d4);
        float* p = Ps + row * PP + d4;
        p[0] = f2tff(v.x); p[1] = f2tff(v.y); p[2] = f2tff(v.z); p[3] = f2tff(v.w);
    }
    __syncthreads();
    uint32_t qa[8][4];
    {
        const float* p0 = Ps + (w * 16 + g4) * PP;
        const float* p1 = p0 + 8 * PP;
#pragma unroll
        for (int ds = 0; ds < 8; ds++) {
            int col = ds * 8 + t4;
            qa[ds][0] = __float_as_uint(p0[col]);
            qa[ds][1] = __float_as_uint(p1[col]);
            qa[ds][2] = __float_as_uint(p0[col + 4]);
            qa[ds][3] = __float_as_uint(p1[col + 4]);
        }
    }

    float o[8][4];
#pragma unroll
    for (int dt = 0; dt < 8; dt++)
#pragma unroll
        for (int j = 0; j < 4; j++) o[dt][j] = 0.f;
    float m0 = -1e30f, m1 = -1e30f, l0 = 0.f, l1 = 0.f;

    float* pw = Ps + w * 16 * PP;

    for (int kt = 0; kt < 32; kt++) {
        __syncthreads();   // qa read / prior-iter Ks,Vt reads complete
#pragma unroll
        for (int i = 0; i < 4; i++) {
            int e = tid + i * 256;           // 1024 float4 chunks
            int row = e >> 4, d4 = (e & 15) << 2;
            size_t g = base + (size_t)(kt * 64 + row) * AH + d4;
            float4 kv = *(const float4*)(g_k + g);
            float4 vv = *(const float4*)(g_v + g);
            float* pk = Ks + row * KP + d4;
            pk[0] = f2tff(kv.x); pk[1] = f2tff(kv.y); pk[2] = f2tff(kv.z); pk[3] = f2tff(kv.w);
            Vt[(d4 + 0) * VPT + row] = f2tff(vv.x);
            Vt[(d4 + 1) * VPT + row] = f2tff(vv.y);
            Vt[(d4 + 2) * VPT + row] = f2tff(vv.z);
            Vt[(d4 + 3) * VPT + row] = f2tff(vv.w);
        }
        __syncthreads();

        // S = Q K^T
        float s[8][4];
#pragma unroll
        for (int nt = 0; nt < 8; nt++)
#pragma unroll
            for (int j = 0; j < 4; j++) s[nt][j] = 0.f;
#pragma unroll
        for (int ds = 0; ds < 8; ds++) {
            int col = ds * 8 + t4;
#pragma unroll
            for (int nt = 0; nt < 8; nt++) {
                uint32_t bf[2];
                const float* p = Ks + (nt * 8 + g4) * KP;
                bf[0] = __float_as_uint(p[col]);
                bf[1] = __float_as_uint(p[col + 4]);
                mma_tf32(s[nt], qa[ds], bf);
            }
        }

        // online softmax (rows g4 and g4+8)
        float mx0 = -1e30f, mx1 = -1e30f;
#pragma unroll
        for (int nt = 0; nt < 8; nt++) {
            mx0 = fmaxf(mx0, fmaxf(s[nt][0], s[nt][1]));
            mx1 = fmaxf(mx1, fmaxf(s[nt][2], s[nt][3]));
        }
#pragma unroll
        for (int off = 1; off <= 2; off <<= 1) {
            mx0 = fmaxf(mx0, __shfl_xor_sync(0xffffffffu, mx0, off));
            mx1 = fmaxf(mx1, __shfl_xor_sync(0xffffffffu, mx1, off));
        }
        float mn0 = fmaxf(m0, mx0 * 0.125f);
        float mn1 = fmaxf(m1, mx1 * 0.125f);
        float a0 = __expf(m0 - mn0), a1 = __expf(m1 - mn1);
        float rs0 = 0.f, rs1 = 0.f;
#pragma unroll
        for (int nt = 0; nt < 8; nt++) {
            s[nt][0] = __expf(s[nt][0] * 0.125f - mn0);
            s[nt][1] = __expf(s[nt][1] * 0.125f - mn0);
            s[nt][2] = __expf(s[nt][2] * 0.125f - mn1);
            s[nt][3] = __expf(s[nt][3] * 0.125f - mn1);
            rs0 += s[nt][0] + s[nt][1];
            rs1 += s[nt][2] + s[nt][3];
        }
#pragma unroll
        for (int off = 1; off <= 2; off <<= 1) {
            rs0 += __shfl_xor_sync(0xffffffffu, rs0, off);
            rs1 += __shfl_xor_sync(0xffffffffu, rs1, off);
        }
        l0 = l0 * a0 + rs0; l1 = l1 * a1 + rs1;
        m0 = mn0; m1 = mn1;
#pragma unroll
        for (int dt = 0; dt < 8; dt++) {
            o[dt][0] *= a0; o[dt][1] *= a0;
            o[dt][2] *= a1; o[dt][3] *= a1;
        }

        // P -> per-warp smem patch (tf32-rounded)
#pragma unroll
        for (int nt = 0; nt < 8; nt++) {
            int col = nt * 8 + 2 * t4;
            *(float2*)(pw + g4 * PP + col) =
                make_float2(__uint_as_float(f2tf(s[nt][0])), __uint_as_float(f2tf(s[nt][1])));
            *(float2*)(pw + (g4 + 8) * PP + col) =
                make_float2(__uint_as_float(f2tf(s[nt][2])), __uint_as_float(f2tf(s[nt][3])));
        }
        __syncwarp();

        // O += P V
#pragma unroll
        for (int ks = 0; ks < 8; ks++) {
            int col = ks * 8 + t4;
            uint32_t pa[4];
            pa[0] = __float_as_uint(pw[g4 * PP + col]);
            pa[1] = __float_as_uint(pw[(g4 + 8) * PP + col]);
            pa[2] = __float_as_uint(pw[g4 * PP + col + 4]);
            pa[3] = __float_as_uint(pw[(g4 + 8) * PP + col + 4]);
#pragma unroll
            for (int dt = 0; dt < 8; dt++) {
                uint32_t bf[2];
                const float* vp = Vt + (dt * 8 + g4) * VPT + ks * 8;
                bf[0] = __float_as_uint(vp[t4]);
                bf[1] = __float_as_uint(vp[t4 + 4]);
                mma_tf32(o[dt], pa, bf);
            }
        }
    }

    // final: normalize + store
    float inv0 = 1.f / l0, inv1 = 1.f / l1;
    const int row = b * SEQ + q0 + w * 16 + g4;
#pragma unroll
    for (int dt = 0; dt < 8; dt++) {
        int col = h * HD + dt * 8 + 2 * t4;
        *(float2*)(out + (size_t)row * (2 * AH) + col) =
            make_float2(o[dt][0] * inv0, o[dt][1] * inv0);
        *(float2*)(out + (size_t)(row + 8) * (2 * AH) + col) =
            make_float2(o[dt][2] * inv1, o[dt][3] * inv1);
    }
}

// ---------------- launch ----------------
extern "C" void kernel_launch(void* const* d_in, const int* in_sizes, int n_in,
                              void* d_out, int out_size)
{
    (void)in_sizes; (void)n_in; (void)out_size;
    const float* x   = (const float*)d_in[0];
    const float* Wq  = (const float*)d_in[1];
    const float* bq  = (const float*)d_in[2];
    const float* Wk  = (const float*)d_in[3];
    const float* bk  = (const float*)d_in[4];
    const float* Wv  = (const float*)d_in[5];
    const float* bv  = (const float*)d_in[6];
    const float* dw  = (const float*)d_in[7];
    const float* pw  = (const float*)d_in[8];
    const float* cb  = (const float*)d_in[9];
    const float* Wck = (const float*)d_in[10];
    const float* bck = (const float*)d_in[11];
    const float* Wco = (const float*)d_in[12];
    const float* bco = (const float*)d_in[13];
    float* out = (float*)d_out;

    float *qp, *kp, *vp, *cop, *kcp, *dwop, *xrp, *wrp;
    cudaGetSymbolAddress((void**)&qp,   g_q);
    cudaGetSymbolAddress((void**)&kp,   g_k);
    cudaGetSymbolAddress((void**)&vp,   g_v);
    cudaGetSymbolAddress((void**)&cop,  g_co);
    cudaGetSymbolAddress((void**)&kcp,  g_kc);
    cudaGetSymbolAddress((void**)&dwop, g_dwo);
    cudaGetSymbolAddress((void**)&xrp,  g_xr);
    cudaGetSymbolAddress((void**)&wrp,  g_wr);

    cudaFuncSetAttribute(gemm_mma_kernel, cudaFuncAttributeMaxDynamicSharedMemorySize,
                         2 * STG_FLTS * 4);
    cudaFuncSetAttribute(attn_mma_kernel, cudaFuncAttributeMaxDynamicSharedMemorySize, 69632);

    // launches ordered so attn is launch index 5 (ncu -s 5 -c 1 captures it)
    const int RN = XN4 + 5 * WN4;
    round_all_kernel<<<(RN + 255) / 256, 256>>>(x, Wq, Wk, Wv, Wco, pw, xrp, wrp);  // 0
    dwconv_kernel<<<(MROWS * HID) / 256, 256>>>(x, dw);                              // 1

    dim3 gg(AH / 128, MROWS / 128);   // (3, 64)
    gemm_mma_kernel<<<gg, 256, 2 * STG_FLTS * 4>>>(xrp,  wrp + 0 * AH * HID, bq,  qp);  // 2
    gemm_mma_kernel<<<gg, 256, 2 * STG_FLTS * 4>>>(xrp,  wrp + 1 * AH * HID, bk,  kp);  // 3
    gemm_mma_kernel<<<gg, 256, 2 * STG_FLTS * 4>>>(xrp,  wrp + 2 * AH * HID, bv,  vp);  // 4
    attn_mma_kernel<<<dim3(SEQ / 128, BSZ * NH), 256, 69632>>>(out);                    // 5
    gemm_mma_kernel<<<gg, 256, 2 * STG_FLTS * 4>>>(xrp,  wrp + 3 * AH * HID, bco, cop); // 6
    gemm_mma_kernel<<<gg, 256, 2 * STG_FLTS * 4>>>(dwop, wrp + 4 * AH * HID, cb,  kcp); // 7
    convmix_kernel<<<MROWS, 384>>>(Wck, bck, out);                                      // 8
}

// round 8
// speedup vs baseline: 1.7869x; 1.0276x over previous
#include <cuda_runtime.h>
#include <cstdint>

#define BSZ 4
#define SEQ 2048
#define HID 768
#define AH  384
#define NH  6
#define HD  64
#define KW  9
#define MROWS (BSZ*SEQ)   // 8192

// ---------------- scratch (no allocs allowed) ----------------
__device__ float g_q  [MROWS*AH];      // tf32-rounded
__device__ float g_k  [MROWS*AH];      // tf32-rounded
__device__ float g_v  [MROWS*AH];      // tf32-rounded
__device__ float g_co [MROWS*AH];      // fp32
__device__ float g_kc [MROWS*AH];      // fp32
__device__ float g_dwo[MROWS*HID];     // tf32-rounded (A operand of kc gemm)
__device__ float g_xr [MROWS*HID];     // x rounded to tf32
__device__ float g_wr [5*AH*HID];      // Wq,Wk,Wv,Wco,pw rounded to tf32

// ================= helpers =================
__device__ __forceinline__ uint32_t smem_u32(const void* p) {
    uint32_t a;
    asm("{ .reg .u64 t; cvta.to.shared.u64 t, %1; cvt.u32.u64 %0, t; }" : "=r"(a) : "l"(p));
    return a;
}
__device__ __forceinline__ uint32_t f2tf(float x) {
    uint32_t r;
    asm("cvt.rna.tf32.f32 %0, %1;" : "=r"(r) : "f"(x));
    return r;
}
__device__ __forceinline__ float f2tff(float x) { return __uint_as_float(f2tf(x)); }

// m16n8k8 tf32 mma: D(16x8,f32) += A(16x8,tf32) * B(8x8,tf32 col-major)
__device__ __forceinline__ void mma_tf32(float* c, const uint32_t* a, const uint32_t* b) {
    asm volatile(
        "mma.sync.aligned.m16n8k8.row.col.f32.tf32.tf32.f32 "
        "{%0,%1,%2,%3}, {%4,%5,%6,%7}, {%8,%9}, {%0,%1,%2,%3};"
        : "+f"(c[0]), "+f"(c[1]), "+f"(c[2]), "+f"(c[3])
        : "r"(a[0]), "r"(a[1]), "r"(a[2]), "r"(a[3]), "r"(b[0]), "r"(b[1]));
}

// ---------------- fused rounding of x + all 5 weights ----------------
#define XN4 (MROWS*HID/4)
#define WN4 (AH*HID/4)
__global__ __launch_bounds__(256) void round_all_kernel(
    const float* __restrict__ x,
    const float* __restrict__ Wq, const float* __restrict__ Wk,
    const float* __restrict__ Wv, const float* __restrict__ Wco,
    const float* __restrict__ pw,
    float* __restrict__ xr, float* __restrict__ wr)
{
    int i = blockIdx.x * 256 + threadIdx.x;
    const float4* src;
    float4* dst;
    int off;
    if (i < XN4) { src = (const float4*)x; dst = (float4*)xr; off = i; }
    else {
        int j = i - XN4;
        int sel = j / WN4;
        off = j - sel * WN4;
        const float* ws[5] = {Wq, Wk, Wv, Wco, pw};
        if (sel >= 5) return;
        src = (const float4*)ws[sel];
        dst = (float4*)(wr + sel * (AH * HID));
    }
    float4 v = src[off];
    float4 r;
    r.x = f2tff(v.x); r.y = f2tff(v.y); r.z = f2tff(v.z); r.w = f2tff(v.w);
    dst[off] = r;
}

// ---------------- tf32 mma GEMM core (shared by both gemm kernels) ----------------
#define APITCH 36
#define STG_FLTS (2*128*APITCH)

__device__ __forceinline__ void gemm_body(
    const float* __restrict__ A, const float* __restrict__ W,
    const float* __restrict__ bias, float* __restrict__ C,
    float* smem, int m0, int n0, bool round_out)
{
    const int tid = threadIdx.x, lane = tid & 31, wid = tid >> 5;
    const int wm = (wid >> 2) * 64;
    const int wn = (wid & 3) * 32;
    const int g4 = lane >> 2, t4 = lane & 3;

    float c[4][4][4];
#pragma unroll
    for (int mt = 0; mt < 4; mt++)
#pragma unroll
        for (int nt = 0; nt < 4; nt++)
#pragma unroll
            for (int j = 0; j < 4; j++) c[mt][nt][j] = 0.f;

    auto load_stage = [&](int s, int kb) {
        float* sb = smem + s * STG_FLTS;
#pragma unroll
        for (int ci = 0; ci < 4; ci++) {
            int e = tid + ci * 256;
            int row = e >> 3, k4 = (e & 7) << 2;
            uint32_t dst = smem_u32(sb + row * APITCH + k4);
            const float* g = A + (size_t)(m0 + row) * HID + kb + k4;
            asm volatile("cp.async.cg.shared.global [%0], [%1], 16;" :: "r"(dst), "l"(g));
        }
#pragma unroll
        for (int ci = 0; ci < 4; ci++) {
            int e = tid + ci * 256;
            int row = e >> 3, k4 = (e & 7) << 2;
            uint32_t dst = smem_u32(sb + 128 * APITCH + row * APITCH + k4);
            const float* g = W + (size_t)(n0 + row) * HID + kb + k4;
            asm volatile("cp.async.cg.shared.global [%0], [%1], 16;" :: "r"(dst), "l"(g));
        }
        asm volatile("cp.async.commit_group;" ::: "memory");
    };

    load_stage(0, 0);
    load_stage(1, 32);

    for (int i = 0; i < 24; i++) {
        const int s = i & 1;
        if (i < 23) asm volatile("cp.async.wait_group 1;" ::: "memory");
        else        asm volatile("cp.async.wait_group 0;" ::: "memory");
        __syncthreads();

        const float* as = smem + s * STG_FLTS;
        const float* bs = as + 128 * APITCH;
#pragma unroll
        for (int ks = 0; ks < 4; ks++) {
            const int col = ks * 8 + t4;
            uint32_t af[4][4], bf[4][2];
#pragma unroll
            for (int mt = 0; mt < 4; mt++) {
                const float* p = as + (wm + mt * 16 + g4) * APITCH;
                af[mt][0] = __float_as_uint(p[col]);
                af[mt][1] = __float_as_uint(p[8 * APITCH + col]);
                af[mt][2] = __float_as_uint(p[col + 4]);
                af[mt][3] = __float_as_uint(p[8 * APITCH + col + 4]);
            }
#pragma unroll
            for (int nt = 0; nt < 4; nt++) {
                const float* p = bs + (wn + nt * 8 + g4) * APITCH;
                bf[nt][0] = __float_as_uint(p[col]);
                bf[nt][1] = __float_as_uint(p[col + 4]);
            }
#pragma unroll
            for (int mt = 0; mt < 4; mt++)
#pragma unroll
                for (int nt = 0; nt < 4; nt++)
                    mma_tf32(c[mt][nt], af[mt], bf[nt]);
        }
        __syncthreads();
        if (i + 2 < 24) load_stage(s, (i + 2) * 32);
    }

#pragma unroll
    for (int mt = 0; mt < 4; mt++) {
        int row = m0 + wm + mt * 16 + g4;
#pragma unroll
        for (int nt = 0; nt < 4; nt++) {
            int col = n0 + wn + nt * 8 + 2 * t4;
            float b0 = __ldg(bias + col), b1 = __ldg(bias + col + 1);
            float v00 = c[mt][nt][0] + b0, v01 = c[mt][nt][1] + b1;
            float v10 = c[mt][nt][2] + b0, v11 = c[mt][nt][3] + b1;
            if (round_out) {
                v00 = f2tff(v00); v01 = f2tff(v01);
                v10 = f2tff(v10); v11 = f2tff(v11);
            }
            *(float2*)(C + (size_t)row * AH + col)       = make_float2(v00, v01);
            *(float2*)(C + (size_t)(row + 8) * AH + col) = make_float2(v10, v11);
        }
    }
}

// batched q/k/v/co GEMM: blockIdx.z selects weight/bias/dst; q,k,v outputs tf32-rounded
__global__ __launch_bounds__(256, 2) void gemm_qkvco_kernel(
    const float* __restrict__ A, const float* __restrict__ wr,
    const float* bq, const float* bk, const float* bv, const float* bco,
    float* q, float* k, float* v, float* co)
{
    extern __shared__ float smem[];
    const int sel = blockIdx.z;
    const float* biases[4] = {bq, bk, bv, bco};
    float* dsts[4] = {q, k, v, co};
    gemm_body(A, wr + (size_t)sel * AH * HID, biases[sel], dsts[sel],
              smem, blockIdx.y * 128, blockIdx.x * 128, sel < 3);
}

// kc GEMM (unrounded output)
__global__ __launch_bounds__(256, 2) void gemm_kc_kernel(
    const float* __restrict__ A, const float* __restrict__ W,
    const float* __restrict__ bias, float* __restrict__ C)
{
    extern __shared__ float smem[];
    gemm_body(A, W, bias, C, smem, blockIdx.y * 128, blockIdx.x * 128, false);
}

// ---------------- depthwise conv (same padding, K=9); output tf32-rounded -------
__global__ __launch_bounds__(256) void dwconv_kernel(const float* __restrict__ x,
                                                     const float* __restrict__ dw)
{
    int idx = blockIdx.x * 256 + threadIdx.x;
    int c = idx % HID;
    int r = idx / HID;
    int s = r % SEQ;
    int b = r / SEQ;
    float acc = 0.f;
#pragma unroll
    for (int kk = 0; kk < KW; kk++) {
        int s2 = s + kk - KW / 2;
        if (s2 >= 0 && s2 < SEQ)
            acc = fmaf(x[(size_t)(b * SEQ + s2) * HID + c], dw[c * KW + kk], acc);
    }
    g_dwo[idx] = f2tff(acc);
}

// ---------------- fused dynamic-span conv ----------------
__global__ __launch_bounds__(384) void convmix_kernel(
    const float* __restrict__ Wck, const float* __restrict__ bck,
    float* __restrict__ out)
{
    __shared__ float ca[AH];
    __shared__ float pr[NH * KW];
    const int r = blockIdx.x;
    const int t = threadIdx.x;

    ca[t] = g_kc[(size_t)r * AH + t] * g_q[(size_t)r * AH + t];
    __syncthreads();

    if (t < NH * KW) {
        const float* w = Wck + t * AH;
        float acc = bck[t];
#pragma unroll 4
        for (int c = 0; c < AH; c++) acc = fmaf(w[c], ca[c], acc);
        pr[t] = acc;
    }
    __syncthreads();

    if (t < NH) {
        float m = -1e30f;
#pragma unroll
        for (int kk = 0; kk < KW; kk++) m = fmaxf(m, pr[t * KW + kk]);
        float e[KW];
        float s = 0.f;
#pragma unroll
        for (int kk = 0; kk < KW; kk++) { e[kk] = __expf(pr[t * KW + kk] - m); s += e[kk]; }
        float inv = 1.f / s;
#pragma unroll
        for (int kk = 0; kk < KW; kk++) pr[t * KW + kk] = e[kk] * inv;
    }
    __syncthreads();

    const int s_ = r % SEQ;
    const int b  = r / SEQ;
    const int h  = t / HD;
    float acc = 0.f;
#pragma unroll
    for (int kk = 0; kk < KW; kk++) {
        int s2 = s_ + kk - KW / 2;
        if (s2 >= 0 && s2 < SEQ)
            acc = fmaf(g_co[(size_t)(b * SEQ + s2) * AH + t], pr[h * KW + kk], acc);
    }
    out[(size_t)r * (2 * AH) + AH + t] = acc;
}

// ---------------- flash attention, tf32 mma.sync; Q/K/V pre-rounded ----------------
// CTA: 128 q-rows, 8 warps, 32 KV tiles of 64 keys.
#define KP  68
#define VPT 68
#define PP  68
// smem floats: Ks 64*68 + Vt 64*68 + Ps 128*68 = 17408 -> 69632 B
__global__ __launch_bounds__(256) void attn_mma_kernel(float* __restrict__ out)
{
    extern __shared__ float smem[];
    float* Ks = smem;
    float* Vt = Ks + 64 * KP;
    float* Ps = Vt + 64 * VPT;

    const int tid = threadIdx.x, lane = tid & 31, w = tid >> 5;
    const int g4 = lane >> 2, t4 = lane & 3;
    const int q0 = blockIdx.x * 128;
    const int b  = blockIdx.y / NH;
    const int h  = blockIdx.y % NH;
    const size_t base = (size_t)b * SEQ * AH + h * HD;

    // ---- stage Q (128 rows, already tf32) into Ps via cp.async, read fragments ----
#pragma unroll
    for (int i = 0; i < 8; i++) {
        int e = tid + i * 256;
        int row = e >> 4, d4 = (e & 15) << 2;
        uint32_t dst = smem_u32(Ps + row * PP + d4);
        const float* g = g_q + base + (size_t)(q0 + row) * AH + d4;
        asm volatile("cp.async.cg.shared.global [%0], [%1], 16;" :: "r"(dst), "l"(g));
    }
    asm volatile("cp.async.commit_group;" ::: "memory");
    asm volatile("cp.async.wait_group 0;" ::: "memory");
    __syncthreads();
    uint32_t qa[8][4];
    {
        const float* p0 = Ps + (w * 16 + g4) * PP;
        const float* p1 = p0 + 8 * PP;
#pragma unroll
        for (int ds = 0; ds < 8; ds++) {
            int col = ds * 8 + t4;
            qa[ds][0] = __float_as_uint(p0[col]);
            qa[ds][1] = __float_as_uint(p1[col]);
            qa[ds][2] = __float_as_uint(p0[col + 4]);
            qa[ds][3] = __float_as_uint(p1[col + 4]);
        }
    }

    float o[8][4];
#pragma unroll
    for (int dt = 0; dt < 8; dt++)
#pragma unroll
        for (int j = 0; j < 4; j++) o[dt][j] = 0.f;
    float m0 = -1e30f, m1 = -1e30f, l0 = 0.f, l1 = 0.f;

    float* pw = Ps + w * 16 * PP;

    for (int kt = 0; kt < 32; kt++) {
        __syncthreads();   // prior-iter Ks/Vt reads complete
#pragma unroll
        for (int i = 0; i < 4; i++) {
            int e = tid + i * 256;
            int row = e >> 4, d4 = (e & 15) << 2;
            size_t g = base + (size_t)(kt * 64 + row) * AH + d4;
            uint32_t kdst = smem_u32(Ks + row * KP + d4);
            asm volatile("cp.async.cg.shared.global [%0], [%1], 16;"
                         :: "r"(kdst), "l"(g_k + g));
            float4 vv = *(const float4*)(g_v + g);
            Vt[(d4 + 0) * VPT + row] = vv.x;
            Vt[(d4 + 1) * VPT + row] = vv.y;
            Vt[(d4 + 2) * VPT + row] = vv.z;
            Vt[(d4 + 3) * VPT + row] = vv.w;
        }
        asm volatile("cp.async.commit_group;" ::: "memory");
        asm volatile("cp.async.wait_group 0;" ::: "memory");
        __syncthreads();

        // S = Q K^T
        float s[8][4];
#pragma unroll
        for (int nt = 0; nt < 8; nt++)
#pragma unroll
            for (int j = 0; j < 4; j++) s[nt][j] = 0.f;
#pragma unroll
        for (int ds = 0; ds < 8; ds++) {
            int col = ds * 8 + t4;
#pragma unroll
            for (int nt = 0; nt < 8; nt++) {
                uint32_t bf[2];
                const float* p = Ks + (nt * 8 + g4) * KP;
                bf[0] = __float_as_uint(p[col]);
                bf[1] = __float_as_uint(p[col + 4]);
                mma_tf32(s[nt], qa[ds], bf);
            }
        }

        // online softmax (rows g4 and g4+8)
        float mx0 = -1e30f, mx1 = -1e30f;
#pragma unroll
        for (int nt = 0; nt < 8; nt++) {
            mx0 = fmaxf(mx0, fmaxf(s[nt][0], s[nt][1]));
            mx1 = fmaxf(mx1, fmaxf(s[nt][2], s[nt][3]));
        }
#pragma unroll
        for (int off = 1; off <= 2; off <<= 1) {
            mx0 = fmaxf(mx0, __shfl_xor_sync(0xffffffffu, mx0, off));
            mx1 = fmaxf(mx1, __shfl_xor_sync(0xffffffffu, mx1, off));
        }
        float mn0 = fmaxf(m0, mx0 * 0.125f);
        float mn1 = fmaxf(m1, mx1 * 0.125f);
        float a0 = __expf(m0 - mn0), a1 = __expf(m1 - mn1);
        float rs0 = 0.f, rs1 = 0.f;
#pragma unroll
        for (int nt = 0; nt < 8; nt++) {
            s[nt][0] = __expf(s[nt][0] * 0.125f - mn0);
            s[nt][1] = __expf(s[nt][1] * 0.125f - mn0);
            s[nt][2] = __expf(s[nt][2] * 0.125f - mn1);
            s[nt][3] = __expf(s[nt][3] * 0.125f - mn1);
            rs0 += s[nt][0] + s[nt][1];
            rs1 += s[nt][2] + s[nt][3];
        }
#pragma unroll
        for (int off = 1; off <= 2; off <<= 1) {
            rs0 += __shfl_xor_sync(0xffffffffu, rs0, off);
            rs1 += __shfl_xor_sync(0xffffffffu, rs1, off);
        }
        l0 = l0 * a0 + rs0; l1 = l1 * a1 + rs1;
        m0 = mn0; m1 = mn1;
#pragma unroll
        for (int dt = 0; dt < 8; dt++) {
            o[dt][0] *= a0; o[dt][1] *= a0;
            o[dt][2] *= a1; o[dt][3] *= a1;
        }

        // P -> per-warp smem patch (tf32-rounded)
#pragma unroll
        for (int nt = 0; nt < 8; nt++) {
            int col = nt * 8 + 2 * t4;
            *(float2*)(pw + g4 * PP + col) =
                make_float2(__uint_as_float(f2tf(s[nt][0])), __uint_as_float(f2tf(s[nt][1])));
            *(float2*)(pw + (g4 + 8) * PP + col) =
                make_float2(__uint_as_float(f2tf(s[nt][2])), __uint_as_float(f2tf(s[nt][3])));
        }
        __syncwarp();

        // O += P V
#pragma unroll
        for (int ks = 0; ks < 8; ks++) {
            int col = ks * 8 + t4;
            uint32_t pa[4];
            pa[0] = __float_as_uint(pw[g4 * PP + col]);
            pa[1] = __float_as_uint(pw[(g4 + 8) * PP + col]);
            pa[2] = __float_as_uint(pw[g4 * PP + col + 4]);
            pa[3] = __float_as_uint(pw[(g4 + 8) * PP + col + 4]);
#pragma unroll
            for (int dt = 0; dt < 8; dt++) {
                uint32_t bf[2];
                const float* vp = Vt + (dt * 8 + g4) * VPT + ks * 8;
                bf[0] = __float_as_uint(vp[t4]);
                bf[1] = __float_as_uint(vp[t4 + 4]);
                mma_tf32(o[dt], pa, bf);
            }
        }
    }

    // final: normalize + store
    float inv0 = 1.f / l0, inv1 = 1.f / l1;
    const int row = b * SEQ + q0 + w * 16 + g4;
#pragma unroll
    for (int dt = 0; dt < 8; dt++) {
        int col = h * HD + dt * 8 + 2 * t4;
        *(float2*)(out + (size_t)row * (2 * AH) + col) =
            make_float2(o[dt][0] * inv0, o[dt][1] * inv0);
        *(float2*)(out + (size_t)(row + 8) * (2 * AH) + col) =
            make_float2(o[dt][2] * inv1, o[dt][3] * inv1);
    }
}

// ---------------- launch ----------------
extern "C" void kernel_launch(void* const* d_in, const int* in_sizes, int n_in,
                              void* d_out, int out_size)
{
    (void)in_sizes; (void)n_in; (void)out_size;
    const float* x   = (const float*)d_in[0];
    const float* Wq  = (const float*)d_in[1];
    const float* bq  = (const float*)d_in[2];
    const float* Wk  = (const float*)d_in[3];
    const float* bk  = (const float*)d_in[4];
    const float* Wv  = (const float*)d_in[5];
    const float* bv  = (const float*)d_in[6];
    const float* dw  = (const float*)d_in[7];
    const float* pw  = (const float*)d_in[8];
    const float* cb  = (const float*)d_in[9];
    const float* Wck = (const float*)d_in[10];
    const float* bck = (const float*)d_in[11];
    const float* Wco = (const float*)d_in[12];
    const float* bco = (const float*)d_in[13];
    float* out = (float*)d_out;

    float *qp, *kp, *vp, *cop, *kcp, *dwop, *xrp, *wrp;
    cudaGetSymbolAddress((void**)&qp,   g_q);
    cudaGetSymbolAddress((void**)&kp,   g_k);
    cudaGetSymbolAddress((void**)&vp,   g_v);
    cudaGetSymbolAddress((void**)&cop,  g_co);
    cudaGetSymbolAddress((void**)&kcp,  g_kc);
    cudaGetSymbolAddress((void**)&dwop, g_dwo);
    cudaGetSymbolAddress((void**)&xrp,  g_xr);
    cudaGetSymbolAddress((void**)&wrp,  g_wr);

    cudaFuncSetAttribute(gemm_qkvco_kernel, cudaFuncAttributeMaxDynamicSharedMemorySize,
                         2 * STG_FLTS * 4);
    cudaFuncSetAttribute(gemm_kc_kernel, cudaFuncAttributeMaxDynamicSharedMemorySize,
                         2 * STG_FLTS * 4);
    cudaFuncSetAttribute(attn_mma_kernel, cudaFuncAttributeMaxDynamicSharedMemorySize, 69632);

    const int RN = XN4 + 5 * WN4;
    // my-index:                                                       (process index = +1)
    round_all_kernel<<<(RN + 255) / 256, 256>>>(x, Wq, Wk, Wv, Wco, pw, xrp, wrp);      // 0
    gemm_qkvco_kernel<<<dim3(AH / 128, MROWS / 128, 4), 256, 2 * STG_FLTS * 4>>>(
        xrp, wrp, bq, bk, bv, bco, qp, kp, vp, cop);                                    // 1
    dwconv_kernel<<<(MROWS * HID) / 256, 256>>>(x, dw);                                 // 2
    gemm_kc_kernel<<<dim3(AH / 128, MROWS / 128), 256, 2 * STG_FLTS * 4>>>(
        dwop, wrp + 4 * (size_t)AH * HID, cb, kcp);                                     // 3
    attn_mma_kernel<<<dim3(SEQ / 128, BSZ * NH), 256, 69632>>>(out);                    // 4 -> proc 5
    convmix_kernel<<<MROWS, 384>>>(Wck, bck, out);                                      // 5
}

// round 9
// speedup vs baseline: 1.8334x; 1.0261x over previous
#include <cuda_runtime.h>
#include <cstdint>

#define BSZ 4
#define SEQ 2048
#define HID 768
#define AH  384
#define NH  6
#define HD  64
#define KW  9
#define MROWS (BSZ*SEQ)   // 8192

// ---------------- scratch (no allocs allowed) ----------------
__device__ float g_q  [MROWS*AH];      // tf32-rounded
__device__ float g_k  [MROWS*AH];      // tf32-rounded
__device__ float g_v  [MROWS*AH];      // tf32-rounded
__device__ float g_co [MROWS*AH];      // fp32
__device__ float g_kc [MROWS*AH];      // fp32
__device__ float g_dwo[MROWS*HID];     // tf32-rounded
__device__ float g_xr [MROWS*HID];     // x rounded to tf32
__device__ float g_wr [5*AH*HID];      // Wq,Wk,Wv,Wco,pw rounded to tf32

// ================= helpers =================
__device__ __forceinline__ uint32_t smem_u32(const void* p) {
    uint32_t a;
    asm("{ .reg .u64 t; cvta.to.shared.u64 t, %1; cvt.u32.u64 %0, t; }" : "=r"(a) : "l"(p));
    return a;
}
__device__ __forceinline__ uint32_t f2tf(float x) {
    uint32_t r;
    asm("cvt.rna.tf32.f32 %0, %1;" : "=r"(r) : "f"(x));
    return r;
}
__device__ __forceinline__ float f2tff(float x) { return __uint_as_float(f2tf(x)); }

__device__ __forceinline__ void mma_tf32(float* c, const uint32_t* a, const uint32_t* b) {
    asm volatile(
        "mma.sync.aligned.m16n8k8.row.col.f32.tf32.tf32.f32 "
        "{%0,%1,%2,%3}, {%4,%5,%6,%7}, {%8,%9}, {%0,%1,%2,%3};"
        : "+f"(c[0]), "+f"(c[1]), "+f"(c[2]), "+f"(c[3])
        : "r"(a[0]), "r"(a[1]), "r"(a[2]), "r"(a[3]), "r"(b[0]), "r"(b[1]));
}

// ---------------- fused rounding of x + all 5 weights ----------------
#define XN4 (MROWS*HID/4)
#define WN4 (AH*HID/4)
__global__ __launch_bounds__(256) void round_all_kernel(
    const float* __restrict__ x,
    const float* __restrict__ Wq, const float* __restrict__ Wk,
    const float* __restrict__ Wv, const float* __restrict__ Wco,
    const float* __restrict__ pw,
    float* __restrict__ xr, float* __restrict__ wr)
{
    int i = blockIdx.x * 256 + threadIdx.x;
    const float4* src;
    float4* dst;
    int off;
    if (i < XN4) { src = (const float4*)x; dst = (float4*)xr; off = i; }
    else {
        int j = i - XN4;
        int sel = j / WN4;
        off = j - sel * WN4;
        const float* ws[5] = {Wq, Wk, Wv, Wco, pw};
        if (sel >= 5) return;
        src = (const float4*)ws[sel];
        dst = (float4*)(wr + sel * (AH * HID));
    }
    float4 v = src[off];
    float4 r;
    r.x = f2tff(v.x); r.y = f2tff(v.y); r.z = f2tff(v.z); r.w = f2tff(v.w);
    dst[off] = r;
}

// ---------------- tf32 mma GEMM core ----------------
#define APITCH 36
#define STG_FLTS (2*128*APITCH)

__device__ __forceinline__ void gemm_body(
    const float* __restrict__ A, const float* __restrict__ W,
    const float* __restrict__ bias, float* __restrict__ C,
    float* smem, int m0, int n0, bool round_out)
{
    const int tid = threadIdx.x, lane = tid & 31, wid = tid >> 5;
    const int wm = (wid >> 2) * 64;
    const int wn = (wid & 3) * 32;
    const int g4 = lane >> 2, t4 = lane & 3;

    float c[4][4][4];
#pragma unroll
    for (int mt = 0; mt < 4; mt++)
#pragma unroll
        for (int nt = 0; nt < 4; nt++)
#pragma unroll
            for (int j = 0; j < 4; j++) c[mt][nt][j] = 0.f;

    auto load_stage = [&](int s, int kb) {
        float* sb = smem + s * STG_FLTS;
#pragma unroll
        for (int ci = 0; ci < 4; ci++) {
            int e = tid + ci * 256;
            int row = e >> 3, k4 = (e & 7) << 2;
            uint32_t dst = smem_u32(sb + row * APITCH + k4);
            const float* g = A + (size_t)(m0 + row) * HID + kb + k4;
            asm volatile("cp.async.cg.shared.global [%0], [%1], 16;" :: "r"(dst), "l"(g));
        }
#pragma unroll
        for (int ci = 0; ci < 4; ci++) {
            int e = tid + ci * 256;
            int row = e >> 3, k4 = (e & 7) << 2;
            uint32_t dst = smem_u32(sb + 128 * APITCH + row * APITCH + k4);
            const float* g = W + (size_t)(n0 + row) * HID + kb + k4;
            asm volatile("cp.async.cg.shared.global [%0], [%1], 16;" :: "r"(dst), "l"(g));
        }
        asm volatile("cp.async.commit_group;" ::: "memory");
    };

    load_stage(0, 0);
    load_stage(1, 32);

    for (int i = 0; i < 24; i++) {
        const int s = i & 1;
        if (i < 23) asm volatile("cp.async.wait_group 1;" ::: "memory");
        else        asm volatile("cp.async.wait_group 0;" ::: "memory");
        __syncthreads();

        const float* as = smem + s * STG_FLTS;
        const float* bs = as + 128 * APITCH;
#pragma unroll
        for (int ks = 0; ks < 4; ks++) {
            const int col = ks * 8 + t4;
            uint32_t af[4][4], bf[4][2];
#pragma unroll
            for (int mt = 0; mt < 4; mt++) {
                const float* p = as + (wm + mt * 16 + g4) * APITCH;
                af[mt][0] = __float_as_uint(p[col]);
                af[mt][1] = __float_as_uint(p[8 * APITCH + col]);
                af[mt][2] = __float_as_uint(p[col + 4]);
                af[mt][3] = __float_as_uint(p[8 * APITCH + col + 4]);
            }
#pragma unroll
            for (int nt = 0; nt < 4; nt++) {
                const float* p = bs + (wn + nt * 8 + g4) * APITCH;
                bf[nt][0] = __float_as_uint(p[col]);
                bf[nt][1] = __float_as_uint(p[col + 4]);
            }
#pragma unroll
            for (int mt = 0; mt < 4; mt++)
#pragma unroll
                for (int nt = 0; nt < 4; nt++)
                    mma_tf32(c[mt][nt], af[mt], bf[nt]);
        }
        __syncthreads();
        if (i + 2 < 24) load_stage(s, (i + 2) * 32);
    }

#pragma unroll
    for (int mt = 0; mt < 4; mt++) {
        int row = m0 + wm + mt * 16 + g4;
#pragma unroll
        for (int nt = 0; nt < 4; nt++) {
            int col = n0 + wn + nt * 8 + 2 * t4;
            float b0 = __ldg(bias + col), b1 = __ldg(bias + col + 1);
            float v00 = c[mt][nt][0] + b0, v01 = c[mt][nt][1] + b1;
            float v10 = c[mt][nt][2] + b0, v11 = c[mt][nt][3] + b1;
            if (round_out) {
                v00 = f2tff(v00); v01 = f2tff(v01);
                v10 = f2tff(v10); v11 = f2tff(v11);
            }
            *(float2*)(C + (size_t)row * AH + col)       = make_float2(v00, v01);
            *(float2*)(C + (size_t)(row + 8) * AH + col) = make_float2(v10, v11);
        }
    }
}

__global__ __launch_bounds__(256, 2) void gemm_qkvco_kernel(
    const float* __restrict__ A, const float* __restrict__ wr,
    const float* bq, const float* bk, const float* bv, const float* bco,
    float* q, float* k, float* v, float* co)
{
    extern __shared__ float smem[];
    const int sel = blockIdx.z;
    const float* biases[4] = {bq, bk, bv, bco};
    float* dsts[4] = {q, k, v, co};
    gemm_body(A, wr + (size_t)sel * AH * HID, biases[sel], dsts[sel],
              smem, blockIdx.y * 128, blockIdx.x * 128, sel < 3);
}

__global__ __launch_bounds__(256, 2) void gemm_kc_kernel(
    const float* __restrict__ A, const float* __restrict__ W,
    const float* __restrict__ bias, float* __restrict__ C)
{
    extern __shared__ float smem[];
    gemm_body(A, W, bias, C, smem, blockIdx.y * 128, blockIdx.x * 128, false);
}

// ---------------- depthwise conv (same padding, K=9); output tf32-rounded -------
__global__ __launch_bounds__(256) void dwconv_kernel(const float* __restrict__ x,
                                                     const float* __restrict__ dw)
{
    int idx = blockIdx.x * 256 + threadIdx.x;
    int c = idx % HID;
    int r = idx / HID;
    int s = r % SEQ;
    int b = r / SEQ;
    float acc = 0.f;
#pragma unroll
    for (int kk = 0; kk < KW; kk++) {
        int s2 = s + kk - KW / 2;
        if (s2 >= 0 && s2 < SEQ)
            acc = fmaf(x[(size_t)(b * SEQ + s2) * HID + c], dw[c * KW + kk], acc);
    }
    g_dwo[idx] = f2tff(acc);
}

// ---------------- fused dynamic-span conv ----------------
__global__ __launch_bounds__(384) void convmix_kernel(
    const float* __restrict__ Wck, const float* __restrict__ bck,
    float* __restrict__ out)
{
    __shared__ float ca[AH];
    __shared__ float pr[NH * KW];
    const int r = blockIdx.x;
    const int t = threadIdx.x;

    ca[t] = g_kc[(size_t)r * AH + t] * g_q[(size_t)r * AH + t];
    __syncthreads();

    if (t < NH * KW) {
        const float* w = Wck + t * AH;
        float acc = bck[t];
#pragma unroll 4
        for (int c = 0; c < AH; c++) acc = fmaf(w[c], ca[c], acc);
        pr[t] = acc;
    }
    __syncthreads();

    if (t < NH) {
        float m = -1e30f;
#pragma unroll
        for (int kk = 0; kk < KW; kk++) m = fmaxf(m, pr[t * KW + kk]);
        float e[KW];
        float s = 0.f;
#pragma unroll
        for (int kk = 0; kk < KW; kk++) { e[kk] = __expf(pr[t * KW + kk] - m); s += e[kk]; }
        float inv = 1.f / s;
#pragma unroll
        for (int kk = 0; kk < KW; kk++) pr[t * KW + kk] = e[kk] * inv;
    }
    __syncthreads();

    const int s_ = r % SEQ;
    const int b  = r / SEQ;
    const int h  = t / HD;
    float acc = 0.f;
#pragma unroll
    for (int kk = 0; kk < KW; kk++) {
        int s2 = s_ + kk - KW / 2;
        if (s2 >= 0 && s2 < SEQ)
            acc = fmaf(g_co[(size_t)(b * SEQ + s2) * AH + t], pr[h * KW + kk], acc);
    }
    out[(size_t)r * (2 * AH) + AH + t] = acc;
}

// ---------------- flash attention, tf32 mma.sync, double-buffered K + reg-V ------------
// CTA: 128 q-rows, 8 warps, 32 KV tiles of 64 keys.
// Ks0/Ks1: [key][d] pitch 68 (double buffer); Vt: [d][key] pitch 68; Ps: Q staging / P patches
#define KP  68
// smem floats: 2*64*68 + 64*68 + 128*68 = 26112 -> 104448 B
__global__ __launch_bounds__(256) void attn_mma_kernel(float* __restrict__ out)
{
    extern __shared__ float smem[];
    float* KsBuf[2];
    KsBuf[0] = smem;
    KsBuf[1] = smem + 64 * KP;
    float* Vt = smem + 2 * 64 * KP;
    float* Ps = Vt + 64 * KP;

    const int tid = threadIdx.x, lane = tid & 31, w = tid >> 5;
    const int g4 = lane >> 2, t4 = lane & 3;
    const int q0 = blockIdx.x * 128;
    const int b  = blockIdx.y / NH;
    const int h  = blockIdx.y % NH;
    const size_t base = (size_t)b * SEQ * AH + h * HD;

    // per-thread gmem/smem addressing for K/V tiles (row = e>>4, d4 = (e&15)<<2)
    int rows[4], d4s[4];
#pragma unroll
    for (int i = 0; i < 4; i++) {
        int e = tid + i * 256;
        rows[i] = e >> 4;
        d4s[i]  = (e & 15) << 2;
    }

    auto load_k = [&](int kt, float* dst) {
#pragma unroll
        for (int i = 0; i < 4; i++) {
            size_t g = base + (size_t)(kt * 64 + rows[i]) * AH + d4s[i];
            uint32_t kdst = smem_u32(dst + rows[i] * KP + d4s[i]);
            asm volatile("cp.async.cg.shared.global [%0], [%1], 16;"
                         :: "r"(kdst), "l"(g_k + g));
        }
        asm volatile("cp.async.commit_group;" ::: "memory");
    };

    // ---- stage Q into Ps via cp.async, read fragments pre-scaled by 1/8 (exact) ----
#pragma unroll
    for (int i = 0; i < 8; i++) {
        int e = tid + i * 256;
        int row = e >> 4, d4 = (e & 15) << 2;
        uint32_t dst = smem_u32(Ps + row * KP + d4);
        const float* g = g_q + base + (size_t)(q0 + row) * AH + d4;
        asm volatile("cp.async.cg.shared.global [%0], [%1], 16;" :: "r"(dst), "l"(g));
    }
    asm volatile("cp.async.commit_group;" ::: "memory");
    asm volatile("cp.async.wait_group 0;" ::: "memory");
    __syncthreads();
    uint32_t qa[8][4];
    {
        const float* p0 = Ps + (w * 16 + g4) * KP;
        const float* p1 = p0 + 8 * KP;
#pragma unroll
        for (int ds = 0; ds < 8; ds++) {
            int col = ds * 8 + t4;
            qa[ds][0] = __float_as_uint(p0[col] * 0.125f);
            qa[ds][1] = __float_as_uint(p1[col] * 0.125f);
            qa[ds][2] = __float_as_uint(p0[col + 4] * 0.125f);
            qa[ds][3] = __float_as_uint(p1[col + 4] * 0.125f);
        }
    }
    __syncthreads();   // Ps fragment reads complete before first P-patch writes

    float o[8][4];
#pragma unroll
    for (int dt = 0; dt < 8; dt++)
#pragma unroll
        for (int j = 0; j < 4; j++) o[dt][j] = 0.f;
    float m0 = -1e30f, m1 = -1e30f, l0 = 0.f, l1 = 0.f;

    float* pw = Ps + w * 16 * KP;

    load_k(0, KsBuf[0]);    // prologue prefetch

    for (int kt = 0; kt < 32; kt++) {
        // issue V loads early (in flight across K-wait + S-MMAs)
        float4 vreg[4];
#pragma unroll
        for (int i = 0; i < 4; i++) {
            size_t g = base + (size_t)(kt * 64 + rows[i]) * AH + d4s[i];
            vreg[i] = *(const float4*)(g_v + g);
        }
        if (kt < 31) load_k(kt + 1, KsBuf[(kt + 1) & 1]);
        if (kt < 31) asm volatile("cp.async.wait_group 1;" ::: "memory");
        else         asm volatile("cp.async.wait_group 0;" ::: "memory");
        __syncthreads();   // K-tile kt visible; prev-iter Vt/pw reads complete

        // S = Q K^T (pre-scaled)
        const float* Ks = KsBuf[kt & 1];
        float s[8][4];
#pragma unroll
        for (int nt = 0; nt < 8; nt++)
#pragma unroll
            for (int j = 0; j < 4; j++) s[nt][j] = 0.f;
#pragma unroll
        for (int ds = 0; ds < 8; ds++) {
            int col = ds * 8 + t4;
#pragma unroll
            for (int nt = 0; nt < 8; nt++) {
                uint32_t bf[2];
                const float* p = Ks + (nt * 8 + g4) * KP;
                bf[0] = __float_as_uint(p[col]);
                bf[1] = __float_as_uint(p[col + 4]);
                mma_tf32(s[nt], qa[ds], bf);
            }
        }

        // online softmax (rows g4 and g4+8)
        float mx0 = -1e30f, mx1 = -1e30f;
#pragma unroll
        for (int nt = 0; nt < 8; nt++) {
            mx0 = fmaxf(mx0, fmaxf(s[nt][0], s[nt][1]));
            mx1 = fmaxf(mx1, fmaxf(s[nt][2], s[nt][3]));
        }
#pragma unroll
        for (int off = 1; off <= 2; off <<= 1) {
            mx0 = fmaxf(mx0, __shfl_xor_sync(0xffffffffu, mx0, off));
            mx1 = fmaxf(mx1, __shfl_xor_sync(0xffffffffu, mx1, off));
        }
        float mn0 = fmaxf(m0, mx0);
        float mn1 = fmaxf(m1, mx1);
        float a0 = __expf(m0 - mn0), a1 = __expf(m1 - mn1);
        float rs0 = 0.f, rs1 = 0.f;
#pragma unroll
        for (int nt = 0; nt < 8; nt++) {
            s[nt][0] = __expf(s[nt][0] - mn0);
            s[nt][1] = __expf(s[nt][1] - mn0);
            s[nt][2] = __expf(s[nt][2] - mn1);
            s[nt][3] = __expf(s[nt][3] - mn1);
            rs0 += s[nt][0] + s[nt][1];
            rs1 += s[nt][2] + s[nt][3];
        }
#pragma unroll
        for (int off = 1; off <= 2; off <<= 1) {
            rs0 += __shfl_xor_sync(0xffffffffu, rs0, off);
            rs1 += __shfl_xor_sync(0xffffffffu, rs1, off);
        }
        l0 = l0 * a0 + rs0; l1 = l1 * a1 + rs1;
        m0 = mn0; m1 = mn1;
#pragma unroll
        for (int dt = 0; dt < 8; dt++) {
            o[dt][0] *= a0; o[dt][1] *= a0;
            o[dt][2] *= a1; o[dt][3] *= a1;
        }

        // store V (transposed) and P patch, then sync before PV
#pragma unroll
        for (int i = 0; i < 4; i++) {
            Vt[(d4s[i] + 0) * KP + rows[i]] = vreg[i].x;
            Vt[(d4s[i] + 1) * KP + rows[i]] = vreg[i].y;
            Vt[(d4s[i] + 2) * KP + rows[i]] = vreg[i].z;
            Vt[(d4s[i] + 3) * KP + rows[i]] = vreg[i].w;
        }
#pragma unroll
        for (int nt = 0; nt < 8; nt++) {
            int col = nt * 8 + 2 * t4;
            *(float2*)(pw + g4 * KP + col) =
                make_float2(__uint_as_float(f2tf(s[nt][0])), __uint_as_float(f2tf(s[nt][1])));
            *(float2*)(pw + (g4 + 8) * KP + col) =
                make_float2(__uint_as_float(f2tf(s[nt][2])), __uint_as_float(f2tf(s[nt][3])));
        }
        __syncthreads();

        // O += P V
#pragma unroll
        for (int ks = 0; ks < 8; ks++) {
            int col = ks * 8 + t4;
            uint32_t pa[4];
            pa[0] = __float_as_uint(pw[g4 * KP + col]);
            pa[1] = __float_as_uint(pw[(g4 + 8) * KP + col]);
            pa[2] = __float_as_uint(pw[g4 * KP + col + 4]);
            pa[3] = __float_as_uint(pw[(g4 + 8) * KP + col + 4]);
#pragma unroll
            for (int dt = 0; dt < 8; dt++) {
                uint32_t bf[2];
                const float* vp = Vt + (dt * 8 + g4) * KP + ks * 8;
                bf[0] = __float_as_uint(vp[t4]);
                bf[1] = __float_as_uint(vp[t4 + 4]);
                mma_tf32(o[dt], pa, bf);
            }
        }
    }

    // final: normalize + store
    float inv0 = 1.f / l0, inv1 = 1.f / l1;
    const int row = b * SEQ + q0 + w * 16 + g4;
#pragma unroll
    for (int dt = 0; dt < 8; dt++) {
        int col = h * HD + dt * 8 + 2 * t4;
        *(float2*)(out + (size_t)row * (2 * AH) + col) =
            make_float2(o[dt][0] * inv0, o[dt][1] * inv0);
        *(float2*)(out + (size_t)(row + 8) * (2 * AH) + col) =
            make_float2(o[dt][2] * inv1, o[dt][3] * inv1);
    }
}

// ---------------- launch ----------------
extern "C" void kernel_launch(void* const* d_in, const int* in_sizes, int n_in,
                              void* d_out, int out_size)
{
    (void)in_sizes; (void)n_in; (void)out_size;
    const float* x   = (const float*)d_in[0];
    const float* Wq  = (const float*)d_in[1];
    const float* bq  = (const float*)d_in[2];
    const float* Wk  = (const float*)d_in[3];
    const float* bk  = (const float*)d_in[4];
    const float* Wv  = (const float*)d_in[5];
    const float* bv  = (const float*)d_in[6];
    const float* dw  = (const float*)d_in[7];
    const float* pw  = (const float*)d_in[8];
    const float* cb  = (const float*)d_in[9];
    const float* Wck = (const float*)d_in[10];
    const float* bck = (const float*)d_in[11];
    const float* Wco = (const float*)d_in[12];
    const float* bco = (const float*)d_in[13];
    float* out = (float*)d_out;

    float *qp, *kp, *vp, *cop, *kcp, *dwop, *xrp, *wrp;
    cudaGetSymbolAddress((void**)&qp,   g_q);
    cudaGetSymbolAddress((void**)&kp,   g_k);
    cudaGetSymbolAddress((void**)&vp,   g_v);
    cudaGetSymbolAddress((void**)&cop,  g_co);
    cudaGetSymbolAddress((void**)&kcp,  g_kc);
    cudaGetSymbolAddress((void**)&dwop, g_dwo);
    cudaGetSymbolAddress((void**)&xrp,  g_xr);
    cudaGetSymbolAddress((void**)&wrp,  g_wr);

    cudaFuncSetAttribute(gemm_qkvco_kernel, cudaFuncAttributeMaxDynamicSharedMemorySize,
                         2 * STG_FLTS * 4);
    cudaFuncSetAttribute(gemm_kc_kernel, cudaFuncAttributeMaxDynamicSharedMemorySize,
                         2 * STG_FLTS * 4);
    cudaFuncSetAttribute(attn_mma_kernel, cudaFuncAttributeMaxDynamicSharedMemorySize, 104448);

    const int RN = XN4 + 5 * WN4;
    // attn at my-index 3 -> process launch #6 -> captured by ncu -s 5 -c 1
    round_all_kernel<<<(RN + 255) / 256, 256>>>(x, Wq, Wk, Wv, Wco, pw, xrp, wrp);      // 0
    gemm_qkvco_kernel<<<dim3(AH / 128, MROWS / 128, 4), 256, 2 * STG_FLTS * 4>>>(
        xrp, wrp, bq, bk, bv, bco, qp, kp, vp, cop);                                    // 1
    dwconv_kernel<<<(MROWS * HID) / 256, 256>>>(x, dw);                                 // 2
    attn_mma_kernel<<<dim3(SEQ / 128, BSZ * NH), 256, 104448>>>(out);                   // 3
    gemm_kc_kernel<<<dim3(AH / 128, MROWS / 128), 256, 2 * STG_FLTS * 4>>>(
        dwop, wrp + 4 * (size_t)AH * HID, cb, kcp);                                     // 4
    convmix_kernel<<<MROWS, 384>>>(Wck, bck, out);                                      // 5
}